// round 9
// baseline (speedup 1.0000x reference)
#include <cuda_runtime.h>

// Problem constants
#define B_  4
#define H_  32
#define S_  2048
#define D_  128
#define BH_ (B_ * H_)          // 128
#define DM_ (H_ * D_)          // 4096
#define M_  (B_ * S_)          // 8192

// Scratch (device globals: no allocation allowed in kernel_launch)
__device__ float g_mem[BH_ * D_ * D_];        // [bh][k][v]  8 MB
__device__ float g_nrm[BH_ * D_];             // [bh][k]
__device__ float g_attn[M_ * DM_];            // [b*S+s][h*D+d]  128 MB

// ---------------------------------------------------------------------------
// helpers: packed f32x2 FMA (FFMA2) — 2x fp32 throughput on sm_103a
// ---------------------------------------------------------------------------
__device__ __forceinline__ float phi1(float x) {
    // elu(x)+1 :  x>0 -> x+1 ; else exp(x)
    return x > 0.f ? x + 1.f : __expf(x);
}

__device__ __forceinline__ unsigned long long fdup(float x) {
    unsigned long long r;
    asm("mov.b64 %0, {%1, %2};" : "=l"(r) : "f"(x), "f"(x));
    return r;
}

__device__ __forceinline__ void ffma2(unsigned long long& acc,
                                      unsigned long long a,
                                      unsigned long long b) {
    asm("fma.rn.f32x2 %0, %1, %2, %0;" : "+l"(acc) : "l"(a), "l"(b));
}

__device__ __forceinline__ float2 f2unpack(unsigned long long v) {
    float2 r;
    asm("mov.b64 {%0, %1}, %2;" : "=f"(r.x), "=f"(r.y) : "l"(v));
    return r;
}

// ---------------------------------------------------------------------------
// Kernel 1: memory[bh] = phiK^T @ V  (128x128, K-dim = S) + normalization sums
// one block per (b,h); 256 threads; thread tile 8x8
// ---------------------------------------------------------------------------
__global__ __launch_bounds__(256) void k_memory(const float* __restrict__ Kin,
                                                const float* __restrict__ Vin)
{
    __shared__ float sK[16][128];
    __shared__ float sV[16][128];

    const int bh  = blockIdx.x;
    const float* Kp = Kin + (size_t)bh * S_ * D_;
    const float* Vp = Vin + (size_t)bh * S_ * D_;
    const int tid = threadIdx.x;
    const int tx  = tid & 15, ty = tid >> 4;
    const int k0  = ty * 8,  v0 = tx * 8;

    unsigned long long acc[8][4];
#pragma unroll
    for (int i = 0; i < 8; i++)
#pragma unroll
        for (int j = 0; j < 4; j++) acc[i][j] = 0ULL;
    float nacc = 0.f;

    for (int s0 = 0; s0 < S_; s0 += 16) {
#pragma unroll
        for (int i = 0; i < 2; i++) {
            int slot = tid + i * 256;
            int r = slot >> 5;
            int c = (slot & 31) << 2;
            float4 kv = *(const float4*)(Kp + (size_t)(s0 + r) * D_ + c);
            kv.x = phi1(kv.x); kv.y = phi1(kv.y);
            kv.z = phi1(kv.z); kv.w = phi1(kv.w);
            *(float4*)&sK[r][c] = kv;
            *(float4*)&sV[r][c] = *(const float4*)(Vp + (size_t)(s0 + r) * D_ + c);
        }
        __syncthreads();

        if (tid < 128) {
#pragma unroll
            for (int r = 0; r < 16; r++) nacc += sK[r][tid];
        }

#pragma unroll
        for (int r = 0; r < 16; r++) {
            float a[8];
            *(float4*)&a[0] = *(float4*)&sK[r][k0];
            *(float4*)&a[4] = *(float4*)&sK[r][k0 + 4];
            ulonglong2 b01 = *(const ulonglong2*)&sV[r][v0];
            ulonglong2 b23 = *(const ulonglong2*)&sV[r][v0 + 4];
            unsigned long long Bp[4] = { b01.x, b01.y, b23.x, b23.y };
#pragma unroll
            for (int i = 0; i < 8; i++) {
                unsigned long long ad = fdup(a[i]);
#pragma unroll
                for (int j = 0; j < 4; j++) ffma2(acc[i][j], ad, Bp[j]);
            }
        }
        __syncthreads();
    }

    float* mp = g_mem + (size_t)bh * D_ * D_;
#pragma unroll
    for (int i = 0; i < 8; i++) {
        float o[8];
#pragma unroll
        for (int j = 0; j < 4; j++) {
            float2 v = f2unpack(acc[i][j]);
            o[2 * j] = v.x; o[2 * j + 1] = v.y;
        }
        *(float4*)(mp + (size_t)(k0 + i) * D_ + v0)     = *(float4*)&o[0];
        *(float4*)(mp + (size_t)(k0 + i) * D_ + v0 + 4) = *(float4*)&o[4];
    }
    if (tid < 128) g_nrm[bh * D_ + tid] = nacc;
}

// ---------------------------------------------------------------------------
// Kernel 2: retrieved = phiQ @ memory, denom = phiQ . norm,
//           attn = gw*retrieved/denom + lw*local, packed to [b,s,h*D+d]
// grid (S/64, BH); 256 threads; thread tile 4(s) x 8(v)
// ---------------------------------------------------------------------------
__global__ __launch_bounds__(256) void k_retrieve(const float* __restrict__ Qin,
                                                  const float* __restrict__ Lin,
                                                  const float* __restrict__ bal)
{
    __shared__ float sQ[64][128];
    __shared__ float sM[16][128];
    __shared__ float sN[128];

    const int bh = blockIdx.y;
    const int s0 = blockIdx.x * 64;
    const int h  = bh & (H_ - 1);
    const int b  = bh >> 5;
    const int tid = threadIdx.x;

    const float* Qp = Qin + (size_t)bh * S_ * D_ + (size_t)s0 * D_;
#pragma unroll
    for (int i = 0; i < 8; i++) {
        int slot = tid + i * 256;
        int r = slot >> 5;
        int c = (slot & 31) << 2;
        float4 q = *(const float4*)(Qp + (size_t)r * D_ + c);
        q.x = phi1(q.x); q.y = phi1(q.y);
        q.z = phi1(q.z); q.w = phi1(q.w);
        *(float4*)&sQ[r][c] = q;
    }
    if (tid < 128) sN[tid] = g_nrm[bh * D_ + tid];

    const int tx  = tid & 15, ty = tid >> 4;
    const int v0  = tx * 8,  sl0 = ty * 4;

    unsigned long long acc[4][4];
#pragma unroll
    for (int i = 0; i < 4; i++)
#pragma unroll
        for (int j = 0; j < 4; j++) acc[i][j] = 0ULL;
    float dacc[4] = {0.f, 0.f, 0.f, 0.f};

    const float* mp = g_mem + (size_t)bh * D_ * D_;

    for (int kc = 0; kc < D_; kc += 16) {
#pragma unroll
        for (int i = 0; i < 2; i++) {
            int slot = tid + i * 256;
            int r = slot >> 5;
            int c = (slot & 31) << 2;
            *(float4*)&sM[r][c] = *(const float4*)(mp + (size_t)(kc + r) * D_ + c);
        }
        __syncthreads();   // first iteration also covers sQ / sN

#pragma unroll
        for (int kk = 0; kk < 16; kk++) {
            ulonglong2 b01 = *(const ulonglong2*)&sM[kk][v0];
            ulonglong2 b23 = *(const ulonglong2*)&sM[kk][v0 + 4];
            unsigned long long Bp[4] = { b01.x, b01.y, b23.x, b23.y };
            float nk = sN[kc + kk];
#pragma unroll
            for (int i = 0; i < 4; i++) {
                float ai = sQ[sl0 + i][kc + kk];
                unsigned long long ad = fdup(ai);
#pragma unroll
                for (int j = 0; j < 4; j++) ffma2(acc[i][j], ad, Bp[j]);
                dacc[i] += ai * nk;
            }
        }
        __syncthreads();
    }

    float bf = bal[h];
    float gw = 1.f / (1.f + __expf(-bf));
    float lw = 1.f / (1.f + __expf(-(1.f - bf)));

    const float* lp = Lin + (size_t)bh * S_ * D_ + (size_t)s0 * D_;
    float* op = g_attn + (size_t)(b * S_ + s0) * DM_ + (size_t)h * D_;

#pragma unroll
    for (int i = 0; i < 4; i++) {
        float r[8];
#pragma unroll
        for (int j = 0; j < 4; j++) {
            float2 v = f2unpack(acc[i][j]);
            r[2 * j] = v.x; r[2 * j + 1] = v.y;
        }
        float rd = gw / dacc[i];  // fold gw into the division
        int sl = sl0 + i;
        float4 l0 = *(const float4*)(lp + (size_t)sl * D_ + v0);
        float4 l1 = *(const float4*)(lp + (size_t)sl * D_ + v0 + 4);
        float4 o0, o1;
        o0.x = r[0] * rd + lw * l0.x;
        o0.y = r[1] * rd + lw * l0.y;
        o0.z = r[2] * rd + lw * l0.z;
        o0.w = r[3] * rd + lw * l0.w;
        o1.x = r[4] * rd + lw * l1.x;
        o1.y = r[5] * rd + lw * l1.y;
        o1.z = r[6] * rd + lw * l1.z;
        o1.w = r[7] * rd + lw * l1.w;
        *(float4*)(op + (size_t)sl * DM_ + v0)     = o0;
        *(float4*)(op + (size_t)sl * DM_ + v0 + 4) = o1;
    }
}

// ---------------------------------------------------------------------------
// Kernel 3: out[m,n] = sum_k attn[m,k] * w_o[n,k]   (M=8192, N=4096, K=4096)
// 128x128 block tile, kc=16, 8x8 per thread, FFMA2 inner loop,
// software-pipelined global loads.
// ---------------------------------------------------------------------------
__global__ __launch_bounds__(256, 2) void k_proj(const float* __restrict__ Wo,
                                                 float* __restrict__ Out)
{
    __shared__ float sA[16][132];   // [k][m], padded, 528B rows (16B aligned)
    __shared__ float sB[16][132];   // [k][n]

    const int n0  = blockIdx.x * 128;
    const int m0  = blockIdx.y * 128;
    const int tid = threadIdx.x;
    const int tx  = tid & 15, ty = tid >> 4;

    unsigned long long acc[8][4];
#pragma unroll
    for (int i = 0; i < 8; i++)
#pragma unroll
        for (int j = 0; j < 4; j++) acc[i][j] = 0ULL;

    // prefetch registers for the software pipeline
    float4 pa[2], pw[2];
    int    pr[2], pk[2];

#pragma unroll
    for (int i = 0; i < 2; i++) {
        int slot = tid + i * 256;
        pr[i] = slot >> 2;
        pk[i] = (slot & 3) << 2;
        pa[i] = *(const float4*)(g_attn + (size_t)(m0 + pr[i]) * DM_ + pk[i]);
        pw[i] = *(const float4*)(Wo     + (size_t)(n0 + pr[i]) * DM_ + pk[i]);
    }

    for (int k0 = 0; k0 < DM_; k0 += 16) {
        // commit prefetched tile to smem (transpose to [k][m])
#pragma unroll
        for (int i = 0; i < 2; i++) {
            int r = pr[i], kq = pk[i];
            sA[kq + 0][r] = pa[i].x; sA[kq + 1][r] = pa[i].y;
            sA[kq + 2][r] = pa[i].z; sA[kq + 3][r] = pa[i].w;
            sB[kq + 0][r] = pw[i].x; sB[kq + 1][r] = pw[i].y;
            sB[kq + 2][r] = pw[i].z; sB[kq + 3][r] = pw[i].w;
        }
        __syncthreads();

        // prefetch next tile while computing this one
        if (k0 + 16 < DM_) {
#pragma unroll
            for (int i = 0; i < 2; i++) {
                pa[i] = *(const float4*)(g_attn + (size_t)(m0 + pr[i]) * DM_ + (k0 + 16) + pk[i]);
                pw[i] = *(const float4*)(Wo     + (size_t)(n0 + pr[i]) * DM_ + (k0 + 16) + pk[i]);
            }
        }

#pragma unroll
        for (int k = 0; k < 16; k++) {
            float a[8];
            *(float4*)&a[0] = *(float4*)&sA[k][ty * 8];
            *(float4*)&a[4] = *(float4*)&sA[k][ty * 8 + 4];
            ulonglong2 b01 = *(const ulonglong2*)&sB[k][tx * 8];
            ulonglong2 b23 = *(const ulonglong2*)&sB[k][tx * 8 + 4];
            unsigned long long Bp[4] = { b01.x, b01.y, b23.x, b23.y };
#pragma unroll
            for (int i = 0; i < 8; i++) {
                unsigned long long ad = fdup(a[i]);
#pragma unroll
                for (int j = 0; j < 4; j++) ffma2(acc[i][j], ad, Bp[j]);
            }
        }
        __syncthreads();
    }

#pragma unroll
    for (int i = 0; i < 8; i++) {
        float o[8];
#pragma unroll
        for (int j = 0; j < 4; j++) {
            float2 v = f2unpack(acc[i][j]);
            o[2 * j] = v.x; o[2 * j + 1] = v.y;
        }
        float* cp = Out + (size_t)(m0 + ty * 8 + i) * DM_ + n0 + tx * 8;
        *(float4*)cp       = *(float4*)&o[0];
        *(float4*)(cp + 4) = *(float4*)&o[4];
    }
}

// ---------------------------------------------------------------------------
// kernel_launch
// inputs: 0=query, 1=key, 2=value, 3=local_attn_outputs, 4=balance, 5=w_o
// ---------------------------------------------------------------------------
extern "C" void kernel_launch(void* const* d_in, const int* in_sizes, int n_in,
                              void* d_out, int out_size)
{
    const float* Q   = (const float*)d_in[0];
    const float* K   = (const float*)d_in[1];
    const float* V   = (const float*)d_in[2];
    const float* L   = (const float*)d_in[3];
    const float* bal = (const float*)d_in[4];
    const float* Wo  = (const float*)d_in[5];
    float* out = (float*)d_out;

    k_memory<<<BH_, 256>>>(K, V);

    dim3 g2(S_ / 64, BH_);
    k_retrieve<<<g2, 256>>>(Q, L, bal);

    dim3 g3(DM_ / 128, M_ / 128);
    k_proj<<<g3, 256>>>(Wo, out);
}

// round 12
// speedup vs baseline: 2.2456x; 2.2456x over previous
#include <cuda_runtime.h>
#include <cuda_bf16.h>
#include <cstdint>

// Problem constants
#define B_  4
#define H_  32
#define S_  2048
#define D_  128
#define BH_ (B_ * H_)          // 128
#define DM_ (H_ * D_)          // 4096
#define M_  (B_ * S_)          // 8192

#define SPLIT_ 4
#define SC_ (S_ / SPLIT_)      // 512

// Scratch (device globals: no allocation allowed in kernel_launch)
__device__ float g_mem[BH_ * D_ * D_];                       // reduced memory  8 MB
__device__ float g_mem_p[SPLIT_ * BH_ * D_ * D_];            // partials       32 MB
__device__ float g_nrm_p[SPLIT_ * BH_ * D_];                 // partial norms
__device__ __nv_bfloat16 g_attn_h[(size_t)M_ * DM_];         // attn hi bf16   64 MB
__device__ __nv_bfloat16 g_attn_l[(size_t)M_ * DM_];         // attn lo bf16   64 MB
__device__ __nv_bfloat16 g_wo_h[(size_t)DM_ * DM_];          // w_o hi bf16    32 MB
__device__ __nv_bfloat16 g_wo_l[(size_t)DM_ * DM_];          // w_o lo bf16    32 MB

// ---------------------------------------------------------------------------
// helpers
// ---------------------------------------------------------------------------
__device__ __forceinline__ float phi1(float x) {
    return x > 0.f ? x + 1.f : __expf(x);
}
__device__ __forceinline__ unsigned long long fdup(float x) {
    unsigned long long r;
    asm("mov.b64 %0, {%1, %2};" : "=l"(r) : "f"(x), "f"(x));
    return r;
}
__device__ __forceinline__ void ffma2(unsigned long long& acc,
                                      unsigned long long a,
                                      unsigned long long b) {
    asm("fma.rn.f32x2 %0, %1, %2, %0;" : "+l"(acc) : "l"(a), "l"(b));
}
__device__ __forceinline__ float2 f2unpack(unsigned long long v) {
    float2 r;
    asm("mov.b64 {%0, %1}, %2;" : "=f"(r.x), "=f"(r.y) : "l"(v));
    return r;
}
__device__ __forceinline__ uint32_t bf2pack(float a, float b) {
    __nv_bfloat162 t;
    t.x = __float2bfloat16(a);
    t.y = __float2bfloat16(b);
    return *reinterpret_cast<uint32_t*>(&t);
}
__device__ __forceinline__ uint32_t s2u(const void* p) {
    uint32_t r;
    asm("{ .reg .u64 t; cvta.to.shared.u64 t, %1; cvt.u32.u64 %0, t; }" : "=r"(r) : "l"(p));
    return r;
}
__device__ __forceinline__ void cp16(uint32_t s, const void* g) {
    asm volatile("cp.async.cg.shared.global [%0], [%1], 16;" :: "r"(s), "l"(g) : "memory");
}
#define CP_COMMIT() asm volatile("cp.async.commit_group;" ::: "memory")
#define CP_WAIT1()  asm volatile("cp.async.wait_group 1;" ::: "memory")

__device__ __forceinline__ void ldx4(uint32_t* r, uint32_t a) {
    asm volatile("ldmatrix.sync.aligned.m8n8.x4.shared.b16 {%0,%1,%2,%3}, [%4];"
                 : "=r"(r[0]), "=r"(r[1]), "=r"(r[2]), "=r"(r[3]) : "r"(a));
}
__device__ __forceinline__ void mma16816(float* c, const uint32_t* a,
                                         uint32_t b0, uint32_t b1) {
    asm volatile(
        "mma.sync.aligned.m16n8k16.row.col.f32.bf16.bf16.f32 "
        "{%0,%1,%2,%3}, {%4,%5,%6,%7}, {%8,%9}, {%0,%1,%2,%3};"
        : "+f"(c[0]), "+f"(c[1]), "+f"(c[2]), "+f"(c[3])
        : "r"(a[0]), "r"(a[1]), "r"(a[2]), "r"(a[3]), "r"(b0), "r"(b1));
}

// ---------------------------------------------------------------------------
// Kernel 0: w_o -> bf16 hi/lo split
// ---------------------------------------------------------------------------
__global__ __launch_bounds__(256) void k_cvt(const float* __restrict__ Wo) {
    size_t i = (size_t)blockIdx.x * 256 + threadIdx.x;   // float4 index
    float4 w = ((const float4*)Wo)[i];
    float hx = __bfloat162float(__float2bfloat16(w.x));
    float hy = __bfloat162float(__float2bfloat16(w.y));
    float hz = __bfloat162float(__float2bfloat16(w.z));
    float hw = __bfloat162float(__float2bfloat16(w.w));
    uint2 hp, lp;
    hp.x = bf2pack(w.x, w.y);           hp.y = bf2pack(w.z, w.w);
    lp.x = bf2pack(w.x - hx, w.y - hy); lp.y = bf2pack(w.z - hz, w.w - hw);
    ((uint2*)g_wo_h)[i] = hp;
    ((uint2*)g_wo_l)[i] = lp;
}

// ---------------------------------------------------------------------------
// Kernel 1: partial memory[chunk][bh] = phiK^T @ V over S-chunk + norm partials
// ---------------------------------------------------------------------------
__global__ __launch_bounds__(256) void k_memory(const float* __restrict__ Kin,
                                                const float* __restrict__ Vin)
{
    __shared__ float sK[16][128];
    __shared__ float sV[16][128];

    const int bh    = blockIdx.x;
    const int chunk = blockIdx.y;
    const float* Kp = Kin + (size_t)bh * S_ * D_ + (size_t)chunk * SC_ * D_;
    const float* Vp = Vin + (size_t)bh * S_ * D_ + (size_t)chunk * SC_ * D_;
    const int tid = threadIdx.x;
    const int tx  = tid & 15, ty = tid >> 4;
    const int k0  = ty * 8,  v0 = tx * 8;

    unsigned long long acc[8][4];
#pragma unroll
    for (int i = 0; i < 8; i++)
#pragma unroll
        for (int j = 0; j < 4; j++) acc[i][j] = 0ULL;
    float nacc = 0.f;

    for (int s0 = 0; s0 < SC_; s0 += 16) {
#pragma unroll
        for (int i = 0; i < 2; i++) {
            int slot = tid + i * 256;
            int r = slot >> 5;
            int c = (slot & 31) << 2;
            float4 kv = *(const float4*)(Kp + (size_t)(s0 + r) * D_ + c);
            kv.x = phi1(kv.x); kv.y = phi1(kv.y);
            kv.z = phi1(kv.z); kv.w = phi1(kv.w);
            *(float4*)&sK[r][c] = kv;
            *(float4*)&sV[r][c] = *(const float4*)(Vp + (size_t)(s0 + r) * D_ + c);
        }
        __syncthreads();

        if (tid < 128) {
#pragma unroll
            for (int r = 0; r < 16; r++) nacc += sK[r][tid];
        }

#pragma unroll
        for (int r = 0; r < 16; r++) {
            float a[8];
            *(float4*)&a[0] = *(float4*)&sK[r][k0];
            *(float4*)&a[4] = *(float4*)&sK[r][k0 + 4];
            ulonglong2 b01 = *(const ulonglong2*)&sV[r][v0];
            ulonglong2 b23 = *(const ulonglong2*)&sV[r][v0 + 4];
            unsigned long long Bp[4] = { b01.x, b01.y, b23.x, b23.y };
#pragma unroll
            for (int i = 0; i < 8; i++) {
                unsigned long long ad = fdup(a[i]);
#pragma unroll
                for (int j = 0; j < 4; j++) ffma2(acc[i][j], ad, Bp[j]);
            }
        }
        __syncthreads();
    }

    float* mp = g_mem_p + ((size_t)chunk * BH_ + bh) * D_ * D_;
#pragma unroll
    for (int i = 0; i < 8; i++) {
        float o[8];
#pragma unroll
        for (int j = 0; j < 4; j++) {
            float2 v = f2unpack(acc[i][j]);
            o[2 * j] = v.x; o[2 * j + 1] = v.y;
        }
        *(float4*)(mp + (size_t)(k0 + i) * D_ + v0)     = *(float4*)&o[0];
        *(float4*)(mp + (size_t)(k0 + i) * D_ + v0 + 4) = *(float4*)&o[4];
    }
    if (tid < 128) g_nrm_p[(chunk * BH_ + bh) * D_ + tid] = nacc;
}

// Reduce the 4 memory partials
__global__ __launch_bounds__(256) void k_mreduce() {
    const int i = blockIdx.x * 256 + threadIdx.x;
    const int Q = BH_ * D_ * D_ / 4;
    const float4* p = (const float4*)g_mem_p;
    float4 a = p[i], b = p[i + Q], c = p[i + 2 * Q], d = p[i + 3 * Q];
    float4 s;
    s.x = (a.x + b.x) + (c.x + d.x);
    s.y = (a.y + b.y) + (c.y + d.y);
    s.z = (a.z + b.z) + (c.z + d.z);
    s.w = (a.w + b.w) + (c.w + d.w);
    ((float4*)g_mem)[i] = s;
}

// ---------------------------------------------------------------------------
// Kernel 2: retrieved = phiQ @ memory, denom, gated combine with local,
//           output packed as bf16 hi/lo  [b,s,h*D+d]
// ---------------------------------------------------------------------------
__global__ __launch_bounds__(256) void k_retrieve(const float* __restrict__ Qin,
                                                  const float* __restrict__ Lin,
                                                  const float* __restrict__ bal)
{
    __shared__ float sQ[64][128];
    __shared__ float sM[16][128];
    __shared__ float sN[128];

    const int bh = blockIdx.y;
    const int s0 = blockIdx.x * 64;
    const int h  = bh & (H_ - 1);
    const int b  = bh >> 5;
    const int tid = threadIdx.x;

    const float* Qp = Qin + (size_t)bh * S_ * D_ + (size_t)s0 * D_;
#pragma unroll
    for (int i = 0; i < 8; i++) {
        int slot = tid + i * 256;
        int r = slot >> 5;
        int c = (slot & 31) << 2;
        float4 q = *(const float4*)(Qp + (size_t)r * D_ + c);
        q.x = phi1(q.x); q.y = phi1(q.y);
        q.z = phi1(q.z); q.w = phi1(q.w);
        *(float4*)&sQ[r][c] = q;
    }
    if (tid < 128) {
        float s = 0.f;
#pragma unroll
        for (int c = 0; c < SPLIT_; c++) s += g_nrm_p[(c * BH_ + bh) * D_ + tid];
        sN[tid] = s;
    }

    const int tx  = tid & 15, ty = tid >> 4;
    const int v0  = tx * 8,  sl0 = ty * 4;

    unsigned long long acc[4][4];
#pragma unroll
    for (int i = 0; i < 4; i++)
#pragma unroll
        for (int j = 0; j < 4; j++) acc[i][j] = 0ULL;
    float dacc[4] = {0.f, 0.f, 0.f, 0.f};

    const float* mp = g_mem + (size_t)bh * D_ * D_;

    for (int kc = 0; kc < D_; kc += 16) {
#pragma unroll
        for (int i = 0; i < 2; i++) {
            int slot = tid + i * 256;
            int r = slot >> 5;
            int c = (slot & 31) << 2;
            *(float4*)&sM[r][c] = *(const float4*)(mp + (size_t)(kc + r) * D_ + c);
        }
        __syncthreads();

#pragma unroll
        for (int kk = 0; kk < 16; kk++) {
            ulonglong2 b01 = *(const ulonglong2*)&sM[kk][v0];
            ulonglong2 b23 = *(const ulonglong2*)&sM[kk][v0 + 4];
            unsigned long long Bp[4] = { b01.x, b01.y, b23.x, b23.y };
            float nk = sN[kc + kk];
#pragma unroll
            for (int i = 0; i < 4; i++) {
                float ai = sQ[sl0 + i][kc + kk];
                unsigned long long ad = fdup(ai);
#pragma unroll
                for (int j = 0; j < 4; j++) ffma2(acc[i][j], ad, Bp[j]);
                dacc[i] += ai * nk;
            }
        }
        __syncthreads();
    }

    float bf = bal[h];
    float gw = 1.f / (1.f + __expf(-bf));
    float lw = 1.f / (1.f + __expf(-(1.f - bf)));

    const float* lp = Lin + (size_t)bh * S_ * D_ + (size_t)s0 * D_;
    __nv_bfloat16* oph = g_attn_h + (size_t)(b * S_ + s0) * DM_ + (size_t)h * D_;
    __nv_bfloat16* opl = g_attn_l + (size_t)(b * S_ + s0) * DM_ + (size_t)h * D_;

#pragma unroll
    for (int i = 0; i < 4; i++) {
        float r[8];
#pragma unroll
        for (int j = 0; j < 4; j++) {
            float2 v = f2unpack(acc[i][j]);
            r[2 * j] = v.x; r[2 * j + 1] = v.y;
        }
        float rd = gw / dacc[i];
        int sl = sl0 + i;
        float4 l0 = *(const float4*)(lp + (size_t)sl * D_ + v0);
        float4 l1 = *(const float4*)(lp + (size_t)sl * D_ + v0 + 4);
        float o[8];
        o[0] = r[0] * rd + lw * l0.x;
        o[1] = r[1] * rd + lw * l0.y;
        o[2] = r[2] * rd + lw * l0.z;
        o[3] = r[3] * rd + lw * l0.w;
        o[4] = r[4] * rd + lw * l1.x;
        o[5] = r[5] * rd + lw * l1.y;
        o[6] = r[6] * rd + lw * l1.z;
        o[7] = r[7] * rd + lw * l1.w;
        float oh[8];
#pragma unroll
        for (int j = 0; j < 8; j++) oh[j] = __bfloat162float(__float2bfloat16(o[j]));
        uint4 hv, lv;
        hv.x = bf2pack(o[0], o[1]); hv.y = bf2pack(o[2], o[3]);
        hv.z = bf2pack(o[4], o[5]); hv.w = bf2pack(o[6], o[7]);
        lv.x = bf2pack(o[0] - oh[0], o[1] - oh[1]);
        lv.y = bf2pack(o[2] - oh[2], o[3] - oh[3]);
        lv.z = bf2pack(o[4] - oh[4], o[5] - oh[5]);
        lv.w = bf2pack(o[6] - oh[6], o[7] - oh[7]);
        *(uint4*)(oph + (size_t)sl * DM_ + v0) = hv;
        *(uint4*)(opl + (size_t)sl * DM_ + v0) = lv;
    }
}

// ---------------------------------------------------------------------------
// Kernel 3: Out[m,n] = sum_k attn[m,k] * w_o[n,k]
// mma.sync m16n8k16 bf16 hi/lo split: D = Ah*Bh + Ah*Bl + Al*Bh
// Block tile 256x128, BK=32, cp.async double buffer, 8 warps (4m x 2n) of 64x64.
// ---------------------------------------------------------------------------
#define BM_ 256
#define BN_ 128
#define BK_ 32
#define STRD_B_ 80                           // padded row stride in BYTES (40 bf16)
#define A_TILE_B_ (BM_ * STRD_B_)            // 20480
#define B_TILE_B_ (BN_ * STRD_B_)            // 10240
#define PBUF_ (2 * A_TILE_B_ + 2 * B_TILE_B_)// 61440
#define PSMEM_ (2 * PBUF_)                   // 122880

__global__ __launch_bounds__(256, 1) void k_proj_mma(float* __restrict__ Out)
{
    extern __shared__ char smem[];
    const uint32_t sbase = s2u(smem);
    const int tid  = threadIdx.x;
    const int lane = tid & 31;
    const int wid  = tid >> 5;
    const int wm   = wid >> 1;               // 0..3
    const int wn   = wid & 1;                // 0..1
    const int m0   = blockIdx.y * BM_;
    const int n0   = blockIdx.x * BN_;

    const __nv_bfloat16* Ah = g_attn_h + (size_t)m0 * DM_;
    const __nv_bfloat16* Al = g_attn_l + (size_t)m0 * DM_;
    const __nv_bfloat16* Bh = g_wo_h   + (size_t)n0 * DM_;
    const __nv_bfloat16* Bl = g_wo_l   + (size_t)n0 * DM_;

    float acc[4][8][4];
#pragma unroll
    for (int i = 0; i < 4; i++)
#pragma unroll
        for (int j = 0; j < 8; j++)
#pragma unroll
            for (int q = 0; q < 4; q++) acc[i][j][q] = 0.f;

    // per-thread load slots
    const int lr = tid >> 2;                 // 0..63 (A: +i*64 rows), B: 0..127 over 2 iters? no:
    const int lc = (tid & 3) * 8;            // k-element offset of 16B chunk

    // ldmatrix fragment addresses (within a buffer)
    const uint32_t aFragOff =
        (uint32_t)(wm * 64 + (lane & 15)) * STRD_B_ + ((lane >> 4) << 4);
    const uint32_t bFragOff =
        (uint32_t)(wn * 64 + (lane & 7) + ((lane >> 4) << 3)) * STRD_B_ +
        ((lane & 8) << 1);                   // ((lane>>3)&1)*16 bytes

    // ---- tile loader: global -> smem buffer bsel, K offset k0 ----
    auto load_tiles = [&](int bsel, int k0) {
        const uint32_t sb = sbase + (uint32_t)bsel * PBUF_;
#pragma unroll
        for (int i = 0; i < 4; i++) {        // A: 256 rows
            int r = lr + i * 64;
            size_t go = (size_t)r * DM_ + k0 + lc;
            uint32_t so = (uint32_t)r * STRD_B_ + (uint32_t)(tid & 3) * 16;
            cp16(sb + so,             Ah + go);
            cp16(sb + A_TILE_B_ + so, Al + go);
        }
#pragma unroll
        for (int i = 0; i < 2; i++) {        // B: 128 rows
            int r = lr + i * 64;
            size_t go = (size_t)r * DM_ + k0 + lc;
            uint32_t so = (uint32_t)r * STRD_B_ + (uint32_t)(tid & 3) * 16;
            cp16(sb + 2 * A_TILE_B_ + so,              Bh + go);
            cp16(sb + 2 * A_TILE_B_ + B_TILE_B_ + so,  Bl + go);
        }
    };

    load_tiles(0, 0);   CP_COMMIT();
    load_tiles(1, BK_); CP_COMMIT();

    for (int it = 0; it < DM_ / BK_; it++) {
        CP_WAIT1();
        __syncthreads();
        const uint32_t sb = sbase + (uint32_t)(it & 1) * PBUF_;

#pragma unroll
        for (int ks = 0; ks < 2; ks++) {
            uint32_t ah[4][4], al[4][4], bh[4][4], bl[4][4];
#pragma unroll
            for (int mt = 0; mt < 4; mt++) {
                uint32_t a = sb + aFragOff + (uint32_t)mt * (16 * STRD_B_) + ks * 32;
                ldx4(ah[mt], a);
                ldx4(al[mt], a + A_TILE_B_);
            }
#pragma unroll
            for (int p = 0; p < 4; p++) {
                uint32_t a = sb + 2 * A_TILE_B_ + bFragOff +
                             (uint32_t)p * (16 * STRD_B_) + ks * 32;
                ldx4(bh[p], a);
                ldx4(bl[p], a + B_TILE_B_);
            }
#pragma unroll
            for (int mt = 0; mt < 4; mt++) {
#pragma unroll
                for (int p = 0; p < 4; p++) {
                    // n-tile 2p  : B regs {0,1};  n-tile 2p+1 : B regs {2,3}
                    mma16816(acc[mt][2 * p],     ah[mt], bh[p][0], bh[p][1]);
                    mma16816(acc[mt][2 * p],     ah[mt], bl[p][0], bl[p][1]);
                    mma16816(acc[mt][2 * p],     al[mt], bh[p][0], bh[p][1]);
                    mma16816(acc[mt][2 * p + 1], ah[mt], bh[p][2], bh[p][3]);
                    mma16816(acc[mt][2 * p + 1], ah[mt], bl[p][2], bl[p][3]);
                    mma16816(acc[mt][2 * p + 1], al[mt], bh[p][2], bh[p][3]);
                }
            }
        }
        __syncthreads();
        if (it + 2 < DM_ / BK_) load_tiles(it & 1, (it + 2) * BK_);
        CP_COMMIT();   // unconditional (empty groups keep wait_group bookkeeping simple)
    }

    // ---- epilogue ----
#pragma unroll
    for (int mt = 0; mt < 4; mt++) {
        int r0 = m0 + wm * 64 + mt * 16 + (lane >> 2);
#pragma unroll
        for (int nt = 0; nt < 8; nt++) {
            int col = n0 + wn * 64 + nt * 8 + (lane & 3) * 2;
            float* p0 = Out + (size_t)r0 * DM_ + col;
            *(float2*)p0              = make_float2(acc[mt][nt][0], acc[mt][nt][1]);
            *(float2*)(p0 + 8 * DM_)  = make_float2(acc[mt][nt][2], acc[mt][nt][3]);
        }
    }
}

// ---------------------------------------------------------------------------
// kernel_launch
// inputs: 0=query, 1=key, 2=value, 3=local_attn_outputs, 4=balance, 5=w_o
// ---------------------------------------------------------------------------
extern "C" void kernel_launch(void* const* d_in, const int* in_sizes, int n_in,
                              void* d_out, int out_size)
{
    const float* Q   = (const float*)d_in[0];
    const float* K   = (const float*)d_in[1];
    const float* V   = (const float*)d_in[2];
    const float* L   = (const float*)d_in[3];
    const float* bal = (const float*)d_in[4];
    const float* Wo  = (const float*)d_in[5];
    float* out = (float*)d_out;

    cudaFuncSetAttribute(k_proj_mma, cudaFuncAttributeMaxDynamicSharedMemorySize, PSMEM_);

    k_cvt<<<(DM_ * DM_) / 4 / 256, 256>>>(Wo);

    dim3 g1(BH_, SPLIT_);
    k_memory<<<g1, 256>>>(K, V);
    k_mreduce<<<BH_ * D_ * D_ / 4 / 256, 256>>>();

    dim3 g2(S_ / 64, BH_);
    k_retrieve<<<g2, 256>>>(Q, L, bal);

    dim3 g3(DM_ / BN_, M_ / BM_);     // 32 x 32
    k_proj_mma<<<g3, 256, PSMEM_>>>(out);
}

// round 13
// speedup vs baseline: 2.8127x; 1.2525x over previous
#include <cuda_runtime.h>
#include <cuda_fp16.h>
#include <cstdint>

// Problem constants
#define B_  4
#define H_  32
#define S_  2048
#define D_  128
#define BH_ (B_ * H_)          // 128
#define DM_ (H_ * D_)          // 4096
#define M_  (B_ * S_)          // 8192

#define SPLIT_ 4
#define SC_ (S_ / SPLIT_)      // 512

// Scratch (device globals: no allocation allowed in kernel_launch)
__device__ float g_mem[BH_ * D_ * D_];                       // reduced memory  8 MB
__device__ float g_mem_p[SPLIT_ * BH_ * D_ * D_];            // partials       32 MB
__device__ float g_nrm_p[SPLIT_ * BH_ * D_];                 // partial norms
__device__ __half g_attn_h[(size_t)M_ * DM_];                // attn hi fp16   64 MB
__device__ __half g_attn_l[(size_t)M_ * DM_];                // attn lo fp16   64 MB
__device__ __half g_wo[(size_t)DM_ * DM_];                   // w_o fp16       32 MB

// ---------------------------------------------------------------------------
// helpers
// ---------------------------------------------------------------------------
__device__ __forceinline__ float phi1(float x) {
    return x > 0.f ? x + 1.f : __expf(x);
}
__device__ __forceinline__ unsigned long long fdup(float x) {
    unsigned long long r;
    asm("mov.b64 %0, {%1, %2};" : "=l"(r) : "f"(x), "f"(x));
    return r;
}
__device__ __forceinline__ void ffma2(unsigned long long& acc,
                                      unsigned long long a,
                                      unsigned long long b) {
    asm("fma.rn.f32x2 %0, %1, %2, %0;" : "+l"(acc) : "l"(a), "l"(b));
}
__device__ __forceinline__ float2 f2unpack(unsigned long long v) {
    float2 r;
    asm("mov.b64 {%0, %1}, %2;" : "=f"(r.x), "=f"(r.y) : "l"(v));
    return r;
}
__device__ __forceinline__ uint32_t h2pack(float a, float b) {
    __half2 t = __floats2half2_rn(a, b);
    return *reinterpret_cast<uint32_t*>(&t);
}
__device__ __forceinline__ uint32_t s2u(const void* p) {
    uint32_t r;
    asm("{ .reg .u64 t; cvta.to.shared.u64 t, %1; cvt.u32.u64 %0, t; }" : "=r"(r) : "l"(p));
    return r;
}
__device__ __forceinline__ void cp16(uint32_t s, const void* g) {
    asm volatile("cp.async.cg.shared.global [%0], [%1], 16;" :: "r"(s), "l"(g) : "memory");
}
#define CP_COMMIT() asm volatile("cp.async.commit_group;" ::: "memory")
#define CP_WAIT1()  asm volatile("cp.async.wait_group 1;" ::: "memory")

__device__ __forceinline__ void ldx4(uint32_t* r, uint32_t a) {
    asm volatile("ldmatrix.sync.aligned.m8n8.x4.shared.b16 {%0,%1,%2,%3}, [%4];"
                 : "=r"(r[0]), "=r"(r[1]), "=r"(r[2]), "=r"(r[3]) : "r"(a));
}
__device__ __forceinline__ void mma16816(float* c, const uint32_t* a,
                                         uint32_t b0, uint32_t b1) {
    asm volatile(
        "mma.sync.aligned.m16n8k16.row.col.f32.f16.f16.f32 "
        "{%0,%1,%2,%3}, {%4,%5,%6,%7}, {%8,%9}, {%0,%1,%2,%3};"
        : "+f"(c[0]), "+f"(c[1]), "+f"(c[2]), "+f"(c[3])
        : "r"(a[0]), "r"(a[1]), "r"(a[2]), "r"(a[3]), "r"(b0), "r"(b1));
}

// ---------------------------------------------------------------------------
// Kernel 0: w_o -> fp16
// ---------------------------------------------------------------------------
__global__ __launch_bounds__(256) void k_cvt(const float* __restrict__ Wo) {
    size_t i = (size_t)blockIdx.x * 256 + threadIdx.x;   // float4 index
    float4 w = ((const float4*)Wo)[i];
    uint2 hp;
    hp.x = h2pack(w.x, w.y);
    hp.y = h2pack(w.z, w.w);
    ((uint2*)g_wo)[i] = hp;
}

// ---------------------------------------------------------------------------
// Kernel 1: partial memory[chunk][bh] = phiK^T @ V over S-chunk + norm partials
// ---------------------------------------------------------------------------
__global__ __launch_bounds__(256) void k_memory(const float* __restrict__ Kin,
                                                const float* __restrict__ Vin)
{
    __shared__ float sK[16][128];
    __shared__ float sV[16][128];

    const int bh    = blockIdx.x;
    const int chunk = blockIdx.y;
    const float* Kp = Kin + (size_t)bh * S_ * D_ + (size_t)chunk * SC_ * D_;
    const float* Vp = Vin + (size_t)bh * S_ * D_ + (size_t)chunk * SC_ * D_;
    const int tid = threadIdx.x;
    const int tx  = tid & 15, ty = tid >> 4;
    const int k0  = ty * 8,  v0 = tx * 8;

    unsigned long long acc[8][4];
#pragma unroll
    for (int i = 0; i < 8; i++)
#pragma unroll
        for (int j = 0; j < 4; j++) acc[i][j] = 0ULL;
    float nacc = 0.f;

    for (int s0 = 0; s0 < SC_; s0 += 16) {
#pragma unroll
        for (int i = 0; i < 2; i++) {
            int slot = tid + i * 256;
            int r = slot >> 5;
            int c = (slot & 31) << 2;
            float4 kv = *(const float4*)(Kp + (size_t)(s0 + r) * D_ + c);
            kv.x = phi1(kv.x); kv.y = phi1(kv.y);
            kv.z = phi1(kv.z); kv.w = phi1(kv.w);
            *(float4*)&sK[r][c] = kv;
            *(float4*)&sV[r][c] = *(const float4*)(Vp + (size_t)(s0 + r) * D_ + c);
        }
        __syncthreads();

        if (tid < 128) {
#pragma unroll
            for (int r = 0; r < 16; r++) nacc += sK[r][tid];
        }

#pragma unroll
        for (int r = 0; r < 16; r++) {
            float a[8];
            *(float4*)&a[0] = *(float4*)&sK[r][k0];
            *(float4*)&a[4] = *(float4*)&sK[r][k0 + 4];
            ulonglong2 b01 = *(const ulonglong2*)&sV[r][v0];
            ulonglong2 b23 = *(const ulonglong2*)&sV[r][v0 + 4];
            unsigned long long Bp[4] = { b01.x, b01.y, b23.x, b23.y };
#pragma unroll
            for (int i = 0; i < 8; i++) {
                unsigned long long ad = fdup(a[i]);
#pragma unroll
                for (int j = 0; j < 4; j++) ffma2(acc[i][j], ad, Bp[j]);
            }
        }
        __syncthreads();
    }

    float* mp = g_mem_p + ((size_t)chunk * BH_ + bh) * D_ * D_;
#pragma unroll
    for (int i = 0; i < 8; i++) {
        float o[8];
#pragma unroll
        for (int j = 0; j < 4; j++) {
            float2 v = f2unpack(acc[i][j]);
            o[2 * j] = v.x; o[2 * j + 1] = v.y;
        }
        *(float4*)(mp + (size_t)(k0 + i) * D_ + v0)     = *(float4*)&o[0];
        *(float4*)(mp + (size_t)(k0 + i) * D_ + v0 + 4) = *(float4*)&o[4];
    }
    if (tid < 128) g_nrm_p[(chunk * BH_ + bh) * D_ + tid] = nacc;
}

// Reduce the 4 memory partials
__global__ __launch_bounds__(256) void k_mreduce() {
    const int i = blockIdx.x * 256 + threadIdx.x;
    const int Q = BH_ * D_ * D_ / 4;
    const float4* p = (const float4*)g_mem_p;
    float4 a = p[i], b = p[i + Q], c = p[i + 2 * Q], d = p[i + 3 * Q];
    float4 s;
    s.x = (a.x + b.x) + (c.x + d.x);
    s.y = (a.y + b.y) + (c.y + d.y);
    s.z = (a.z + b.z) + (c.z + d.z);
    s.w = (a.w + b.w) + (c.w + d.w);
    ((float4*)g_mem)[i] = s;
}

// ---------------------------------------------------------------------------
// Kernel 2: retrieved = phiQ @ memory, denom, gated combine with local,
//           output packed as fp16 hi/lo  [b,s,h*D+d]
// ---------------------------------------------------------------------------
__global__ __launch_bounds__(256) void k_retrieve(const float* __restrict__ Qin,
                                                  const float* __restrict__ Lin,
                                                  const float* __restrict__ bal)
{
    __shared__ float sQ[64][128];
    __shared__ float sM[16][128];
    __shared__ float sN[128];

    const int bh = blockIdx.y;
    const int s0 = blockIdx.x * 64;
    const int h  = bh & (H_ - 1);
    const int b  = bh >> 5;
    const int tid = threadIdx.x;

    const float* Qp = Qin + (size_t)bh * S_ * D_ + (size_t)s0 * D_;
#pragma unroll
    for (int i = 0; i < 8; i++) {
        int slot = tid + i * 256;
        int r = slot >> 5;
        int c = (slot & 31) << 2;
        float4 q = *(const float4*)(Qp + (size_t)r * D_ + c);
        q.x = phi1(q.x); q.y = phi1(q.y);
        q.z = phi1(q.z); q.w = phi1(q.w);
        *(float4*)&sQ[r][c] = q;
    }
    if (tid < 128) {
        float s = 0.f;
#pragma unroll
        for (int c = 0; c < SPLIT_; c++) s += g_nrm_p[(c * BH_ + bh) * D_ + tid];
        sN[tid] = s;
    }

    const int tx  = tid & 15, ty = tid >> 4;
    const int v0  = tx * 8,  sl0 = ty * 4;

    unsigned long long acc[4][4];
#pragma unroll
    for (int i = 0; i < 4; i++)
#pragma unroll
        for (int j = 0; j < 4; j++) acc[i][j] = 0ULL;
    float dacc[4] = {0.f, 0.f, 0.f, 0.f};

    const float* mp = g_mem + (size_t)bh * D_ * D_;

    for (int kc = 0; kc < D_; kc += 16) {
#pragma unroll
        for (int i = 0; i < 2; i++) {
            int slot = tid + i * 256;
            int r = slot >> 5;
            int c = (slot & 31) << 2;
            *(float4*)&sM[r][c] = *(const float4*)(mp + (size_t)(kc + r) * D_ + c);
        }
        __syncthreads();

#pragma unroll
        for (int kk = 0; kk < 16; kk++) {
            ulonglong2 b01 = *(const ulonglong2*)&sM[kk][v0];
            ulonglong2 b23 = *(const ulonglong2*)&sM[kk][v0 + 4];
            unsigned long long Bp[4] = { b01.x, b01.y, b23.x, b23.y };
            float nk = sN[kc + kk];
#pragma unroll
            for (int i = 0; i < 4; i++) {
                float ai = sQ[sl0 + i][kc + kk];
                unsigned long long ad = fdup(ai);
#pragma unroll
                for (int j = 0; j < 4; j++) ffma2(acc[i][j], ad, Bp[j]);
                dacc[i] += ai * nk;
            }
        }
        __syncthreads();
    }

    float bf = bal[h];
    float gw = 1.f / (1.f + __expf(-bf));
    float lw = 1.f / (1.f + __expf(-(1.f - bf)));

    const float* lp = Lin + (size_t)bh * S_ * D_ + (size_t)s0 * D_;
    __half* oph = g_attn_h + (size_t)(b * S_ + s0) * DM_ + (size_t)h * D_;
    __half* opl = g_attn_l + (size_t)(b * S_ + s0) * DM_ + (size_t)h * D_;

#pragma unroll
    for (int i = 0; i < 4; i++) {
        float r[8];
#pragma unroll
        for (int j = 0; j < 4; j++) {
            float2 v = f2unpack(acc[i][j]);
            r[2 * j] = v.x; r[2 * j + 1] = v.y;
        }
        float rd = gw / dacc[i];
        int sl = sl0 + i;
        float4 l0 = *(const float4*)(lp + (size_t)sl * D_ + v0);
        float4 l1 = *(const float4*)(lp + (size_t)sl * D_ + v0 + 4);
        float o[8];
        o[0] = r[0] * rd + lw * l0.x;
        o[1] = r[1] * rd + lw * l0.y;
        o[2] = r[2] * rd + lw * l0.z;
        o[3] = r[3] * rd + lw * l0.w;
        o[4] = r[4] * rd + lw * l1.x;
        o[5] = r[5] * rd + lw * l1.y;
        o[6] = r[6] * rd + lw * l1.z;
        o[7] = r[7] * rd + lw * l1.w;
        float oh[8];
#pragma unroll
        for (int j = 0; j < 8; j++) oh[j] = __half2float(__float2half_rn(o[j]));
        uint4 hv, lv;
        hv.x = h2pack(o[0], o[1]); hv.y = h2pack(o[2], o[3]);
        hv.z = h2pack(o[4], o[5]); hv.w = h2pack(o[6], o[7]);
        lv.x = h2pack(o[0] - oh[0], o[1] - oh[1]);
        lv.y = h2pack(o[2] - oh[2], o[3] - oh[3]);
        lv.z = h2pack(o[4] - oh[4], o[5] - oh[5]);
        lv.w = h2pack(o[6] - oh[6], o[7] - oh[7]);
        *(uint4*)(oph + (size_t)sl * DM_ + v0) = hv;
        *(uint4*)(opl + (size_t)sl * DM_ + v0) = lv;
    }
}

// ---------------------------------------------------------------------------
// Kernel 3: Out[m,n] = sum_k attn[m,k] * w_o[n,k]
// fp16 mma.sync m16n8k16, split-A 2-pass: D = Ah*B + Al*B  (B = fp16 w_o)
// Block tile 256x128, BK=32, cp.async double buffer, 8 warps (4m x 2n) of 64x64.
// Pass-major MMA ordering: same-accumulator MMAs are 32 instructions apart.
// ---------------------------------------------------------------------------
#define BM_ 256
#define BN_ 128
#define BK_ 32
#define STRD_B_ 80                           // padded row stride in BYTES (40 fp16)
#define A_TILE_B_ (BM_ * STRD_B_)            // 20480
#define B_TILE_B_ (BN_ * STRD_B_)            // 10240
#define PBUF_ (2 * A_TILE_B_ + B_TILE_B_)    // 51200
#define PSMEM_ (2 * PBUF_)                   // 102400

__global__ __launch_bounds__(256, 1) void k_proj_mma(float* __restrict__ Out)
{
    extern __shared__ char smem[];
    const uint32_t sbase = s2u(smem);
    const int tid  = threadIdx.x;
    const int lane = tid & 31;
    const int wid  = tid >> 5;
    const int wm   = wid >> 1;               // 0..3
    const int wn   = wid & 1;                // 0..1
    const int m0   = blockIdx.y * BM_;
    const int n0   = blockIdx.x * BN_;

    const __half* Ah = g_attn_h + (size_t)m0 * DM_;
    const __half* Al = g_attn_l + (size_t)m0 * DM_;
    const __half* Bw = g_wo     + (size_t)n0 * DM_;

    float acc[4][8][4];
#pragma unroll
    for (int i = 0; i < 4; i++)
#pragma unroll
        for (int j = 0; j < 8; j++)
#pragma unroll
            for (int q = 0; q < 4; q++) acc[i][j][q] = 0.f;

    // per-thread load slots (4 threads x 16B cover one 64B row of BK=32 fp16)
    const int lr = tid >> 2;                 // 0..63
    const int lc = (tid & 3) * 8;            // k-element offset of 16B chunk

    // ldmatrix fragment addresses (within a buffer)
    const uint32_t aFragOff =
        (uint32_t)(wm * 64 + (lane & 15)) * STRD_B_ + ((lane >> 4) << 4);
    const uint32_t bFragOff =
        (uint32_t)(wn * 64 + (lane & 7) + ((lane >> 4) << 3)) * STRD_B_ +
        ((lane & 8) << 1);

    auto load_tiles = [&](int bsel, int k0) {
        const uint32_t sb = sbase + (uint32_t)bsel * PBUF_;
#pragma unroll
        for (int i = 0; i < 4; i++) {        // A: 256 rows (hi + lo)
            int r = lr + i * 64;
            size_t go = (size_t)r * DM_ + k0 + lc;
            uint32_t so = (uint32_t)r * STRD_B_ + (uint32_t)(tid & 3) * 16;
            cp16(sb + so,             Ah + go);
            cp16(sb + A_TILE_B_ + so, Al + go);
        }
#pragma unroll
        for (int i = 0; i < 2; i++) {        // B: 128 rows
            int r = lr + i * 64;
            size_t go = (size_t)r * DM_ + k0 + lc;
            uint32_t so = (uint32_t)r * STRD_B_ + (uint32_t)(tid & 3) * 16;
            cp16(sb + 2 * A_TILE_B_ + so, Bw + go);
        }
    };

    load_tiles(0, 0);   CP_COMMIT();
    load_tiles(1, BK_); CP_COMMIT();

    for (int it = 0; it < DM_ / BK_; it++) {
        CP_WAIT1();
        __syncthreads();
        const uint32_t sb = sbase + (uint32_t)(it & 1) * PBUF_;

#pragma unroll
        for (int ks = 0; ks < 2; ks++) {
            uint32_t ah[4][4], al[4][4], bw[4][4];
#pragma unroll
            for (int mt = 0; mt < 4; mt++) {
                uint32_t a = sb + aFragOff + (uint32_t)mt * (16 * STRD_B_) + ks * 32;
                ldx4(ah[mt], a);
                ldx4(al[mt], a + A_TILE_B_);
            }
#pragma unroll
            for (int p = 0; p < 4; p++) {
                uint32_t a = sb + 2 * A_TILE_B_ + bFragOff +
                             (uint32_t)p * (16 * STRD_B_) + ks * 32;
                ldx4(bw[p], a);
            }
            // pass 1: Ah * B  (each accumulator touched exactly once)
#pragma unroll
            for (int mt = 0; mt < 4; mt++) {
#pragma unroll
                for (int p = 0; p < 4; p++) {
                    mma16816(acc[mt][2 * p],     ah[mt], bw[p][0], bw[p][1]);
                    mma16816(acc[mt][2 * p + 1], ah[mt], bw[p][2], bw[p][3]);
                }
            }
            // pass 2: Al * B  (32 MMAs since the last write to each acc)
#pragma unroll
            for (int mt = 0; mt < 4; mt++) {
#pragma unroll
                for (int p = 0; p < 4; p++) {
                    mma16816(acc[mt][2 * p],     al[mt], bw[p][0], bw[p][1]);
                    mma16816(acc[mt][2 * p + 1], al[mt], bw[p][2], bw[p][3]);
                }
            }
        }
        __syncthreads();
        if (it + 2 < DM_ / BK_) load_tiles(it & 1, (it + 2) * BK_);
        CP_COMMIT();
    }

    // ---- epilogue ----
#pragma unroll
    for (int mt = 0; mt < 4; mt++) {
        int r0 = m0 + wm * 64 + mt * 16 + (lane >> 2);
#pragma unroll
        for (int nt = 0; nt < 8; nt++) {
            int col = n0 + wn * 64 + nt * 8 + (lane & 3) * 2;
            float* p0 = Out + (size_t)r0 * DM_ + col;
            *(float2*)p0              = make_float2(acc[mt][nt][0], acc[mt][nt][1]);
            *(float2*)(p0 + 8 * DM_)  = make_float2(acc[mt][nt][2], acc[mt][nt][3]);
        }
    }
}

// ---------------------------------------------------------------------------
// kernel_launch
// inputs: 0=query, 1=key, 2=value, 3=local_attn_outputs, 4=balance, 5=w_o
// ---------------------------------------------------------------------------
extern "C" void kernel_launch(void* const* d_in, const int* in_sizes, int n_in,
                              void* d_out, int out_size)
{
    const float* Q   = (const float*)d_in[0];
    const float* K   = (const float*)d_in[1];
    const float* V   = (const float*)d_in[2];
    const float* L   = (const float*)d_in[3];
    const float* bal = (const float*)d_in[4];
    const float* Wo  = (const float*)d_in[5];
    float* out = (float*)d_out;

    cudaFuncSetAttribute(k_proj_mma, cudaFuncAttributeMaxDynamicSharedMemorySize, PSMEM_);

    k_cvt<<<(DM_ * DM_) / 4 / 256, 256>>>(Wo);

    dim3 g1(BH_, SPLIT_);
    k_memory<<<g1, 256>>>(K, V);
    k_mreduce<<<BH_ * D_ * D_ / 4 / 256, 256>>>();

    dim3 g2(S_ / 64, BH_);
    k_retrieve<<<g2, 256>>>(Q, L, bal);

    dim3 g3(DM_ / BN_, M_ / BM_);     // 32 x 32
    k_proj_mma<<<g3, 256, PSMEM_>>>(out);
}

// round 14
// speedup vs baseline: 3.9616x; 1.4085x over previous
#include <cuda_runtime.h>
#include <cuda_fp16.h>
#include <cstdint>

// Problem constants
#define B_  4
#define H_  32
#define S_  2048
#define D_  128
#define BH_ (B_ * H_)          // 128
#define DM_ (H_ * D_)          // 4096
#define M_  (B_ * S_)          // 8192

#define SPLIT_ 8
#define SC_ (S_ / SPLIT_)      // 256

// Scratch (device globals: no allocation allowed in kernel_launch)
__device__ float g_mem[BH_ * D_ * D_];                       // reduced memory  8 MB
__device__ float g_mem_p[SPLIT_ * BH_ * D_ * D_];            // partials       64 MB
__device__ float g_nrm_p[SPLIT_ * BH_ * D_];                 // partial norms
__device__ __half g_attn[(size_t)M_ * DM_];                  // attn fp16      64 MB
__device__ __half g_wo[(size_t)DM_ * DM_];                   // w_o fp16       32 MB

// ---------------------------------------------------------------------------
// helpers
// ---------------------------------------------------------------------------
__device__ __forceinline__ float phi1(float x) {
    return x > 0.f ? x + 1.f : __expf(x);
}
__device__ __forceinline__ unsigned long long fdup(float x) {
    unsigned long long r;
    asm("mov.b64 %0, {%1, %2};" : "=l"(r) : "f"(x), "f"(x));
    return r;
}
__device__ __forceinline__ void ffma2(unsigned long long& acc,
                                      unsigned long long a,
                                      unsigned long long b) {
    asm("fma.rn.f32x2 %0, %1, %2, %0;" : "+l"(acc) : "l"(a), "l"(b));
}
__device__ __forceinline__ float2 f2unpack(unsigned long long v) {
    float2 r;
    asm("mov.b64 {%0, %1}, %2;" : "=f"(r.x), "=f"(r.y) : "l"(v));
    return r;
}
__device__ __forceinline__ uint32_t h2pack(float a, float b) {
    __half2 t = __floats2half2_rn(a, b);
    return *reinterpret_cast<uint32_t*>(&t);
}
__device__ __forceinline__ uint32_t s2u(const void* p) {
    uint32_t r;
    asm("{ .reg .u64 t; cvta.to.shared.u64 t, %1; cvt.u32.u64 %0, t; }" : "=r"(r) : "l"(p));
    return r;
}
__device__ __forceinline__ void cp16(uint32_t s, const void* g) {
    asm volatile("cp.async.cg.shared.global [%0], [%1], 16;" :: "r"(s), "l"(g) : "memory");
}
#define CP_COMMIT() asm volatile("cp.async.commit_group;" ::: "memory")
#define CP_WAIT1()  asm volatile("cp.async.wait_group 1;" ::: "memory")

__device__ __forceinline__ void ldx4(uint32_t* r, uint32_t a) {
    asm volatile("ldmatrix.sync.aligned.m8n8.x4.shared.b16 {%0,%1,%2,%3}, [%4];"
                 : "=r"(r[0]), "=r"(r[1]), "=r"(r[2]), "=r"(r[3]) : "r"(a));
}
__device__ __forceinline__ void mma16816(float* c, const uint32_t* a,
                                         uint32_t b0, uint32_t b1) {
    asm volatile(
        "mma.sync.aligned.m16n8k16.row.col.f32.f16.f16.f32 "
        "{%0,%1,%2,%3}, {%4,%5,%6,%7}, {%8,%9}, {%0,%1,%2,%3};"
        : "+f"(c[0]), "+f"(c[1]), "+f"(c[2]), "+f"(c[3])
        : "r"(a[0]), "r"(a[1]), "r"(a[2]), "r"(a[3]), "r"(b0), "r"(b1));
}

// ---------------------------------------------------------------------------
// Kernel 0: w_o -> fp16
// ---------------------------------------------------------------------------
__global__ __launch_bounds__(256) void k_cvt(const float* __restrict__ Wo) {
    size_t i = (size_t)blockIdx.x * 256 + threadIdx.x;   // float4 index
    float4 w = ((const float4*)Wo)[i];
    uint2 hp;
    hp.x = h2pack(w.x, w.y);
    hp.y = h2pack(w.z, w.w);
    ((uint2*)g_wo)[i] = hp;
}

// ---------------------------------------------------------------------------
// Kernel 1: partial memory[chunk][bh] = phiK^T @ V over S-chunk + norm partials
// ---------------------------------------------------------------------------
__global__ __launch_bounds__(256) void k_memory(const float* __restrict__ Kin,
                                                const float* __restrict__ Vin)
{
    __shared__ float sK[16][128];
    __shared__ float sV[16][128];

    const int bh    = blockIdx.x;
    const int chunk = blockIdx.y;
    const float* Kp = Kin + (size_t)bh * S_ * D_ + (size_t)chunk * SC_ * D_;
    const float* Vp = Vin + (size_t)bh * S_ * D_ + (size_t)chunk * SC_ * D_;
    const int tid = threadIdx.x;
    const int tx  = tid & 15, ty = tid >> 4;
    const int k0  = ty * 8,  v0 = tx * 8;

    unsigned long long acc[8][4];
#pragma unroll
    for (int i = 0; i < 8; i++)
#pragma unroll
        for (int j = 0; j < 4; j++) acc[i][j] = 0ULL;
    float nacc = 0.f;

    for (int s0 = 0; s0 < SC_; s0 += 16) {
#pragma unroll
        for (int i = 0; i < 2; i++) {
            int slot = tid + i * 256;
            int r = slot >> 5;
            int c = (slot & 31) << 2;
            float4 kv = *(const float4*)(Kp + (size_t)(s0 + r) * D_ + c);
            kv.x = phi1(kv.x); kv.y = phi1(kv.y);
            kv.z = phi1(kv.z); kv.w = phi1(kv.w);
            *(float4*)&sK[r][c] = kv;
            *(float4*)&sV[r][c] = *(const float4*)(Vp + (size_t)(s0 + r) * D_ + c);
        }
        __syncthreads();

        if (tid < 128) {
#pragma unroll
            for (int r = 0; r < 16; r++) nacc += sK[r][tid];
        }

#pragma unroll
        for (int r = 0; r < 16; r++) {
            float a[8];
            *(float4*)&a[0] = *(float4*)&sK[r][k0];
            *(float4*)&a[4] = *(float4*)&sK[r][k0 + 4];
            ulonglong2 b01 = *(const ulonglong2*)&sV[r][v0];
            ulonglong2 b23 = *(const ulonglong2*)&sV[r][v0 + 4];
            unsigned long long Bp[4] = { b01.x, b01.y, b23.x, b23.y };
#pragma unroll
            for (int i = 0; i < 8; i++) {
                unsigned long long ad = fdup(a[i]);
#pragma unroll
                for (int j = 0; j < 4; j++) ffma2(acc[i][j], ad, Bp[j]);
            }
        }
        __syncthreads();
    }

    float* mp = g_mem_p + ((size_t)chunk * BH_ + bh) * D_ * D_;
#pragma unroll
    for (int i = 0; i < 8; i++) {
        float o[8];
#pragma unroll
        for (int j = 0; j < 4; j++) {
            float2 v = f2unpack(acc[i][j]);
            o[2 * j] = v.x; o[2 * j + 1] = v.y;
        }
        *(float4*)(mp + (size_t)(k0 + i) * D_ + v0)     = *(float4*)&o[0];
        *(float4*)(mp + (size_t)(k0 + i) * D_ + v0 + 4) = *(float4*)&o[4];
    }
    if (tid < 128) g_nrm_p[(chunk * BH_ + bh) * D_ + tid] = nacc;
}

// Reduce the SPLIT_ memory partials
__global__ __launch_bounds__(256) void k_mreduce() {
    const int i = blockIdx.x * 256 + threadIdx.x;
    const int Q = BH_ * D_ * D_ / 4;
    const float4* p = (const float4*)g_mem_p;
    float4 s = p[i];
#pragma unroll
    for (int c = 1; c < SPLIT_; c++) {
        float4 t = p[i + c * Q];
        s.x += t.x; s.y += t.y; s.z += t.z; s.w += t.w;
    }
    ((float4*)g_mem)[i] = s;
}

// ---------------------------------------------------------------------------
// Kernel 2: retrieved = phiQ @ memory, denom, gated combine with local,
//           output fp16  [b,s,h*D+d]
// ---------------------------------------------------------------------------
__global__ __launch_bounds__(256) void k_retrieve(const float* __restrict__ Qin,
                                                  const float* __restrict__ Lin,
                                                  const float* __restrict__ bal)
{
    __shared__ float sQ[64][128];
    __shared__ float sM[16][128];
    __shared__ float sN[128];

    const int bh = blockIdx.y;
    const int s0 = blockIdx.x * 64;
    const int h  = bh & (H_ - 1);
    const int b  = bh >> 5;
    const int tid = threadIdx.x;

    const float* Qp = Qin + (size_t)bh * S_ * D_ + (size_t)s0 * D_;
#pragma unroll
    for (int i = 0; i < 8; i++) {
        int slot = tid + i * 256;
        int r = slot >> 5;
        int c = (slot & 31) << 2;
        float4 q = *(const float4*)(Qp + (size_t)r * D_ + c);
        q.x = phi1(q.x); q.y = phi1(q.y);
        q.z = phi1(q.z); q.w = phi1(q.w);
        *(float4*)&sQ[r][c] = q;
    }
    if (tid < 128) {
        float s = 0.f;
#pragma unroll
        for (int c = 0; c < SPLIT_; c++) s += g_nrm_p[(c * BH_ + bh) * D_ + tid];
        sN[tid] = s;
    }

    const int tx  = tid & 15, ty = tid >> 4;
    const int v0  = tx * 8,  sl0 = ty * 4;

    unsigned long long acc[4][4];
#pragma unroll
    for (int i = 0; i < 4; i++)
#pragma unroll
        for (int j = 0; j < 4; j++) acc[i][j] = 0ULL;
    float dacc[4] = {0.f, 0.f, 0.f, 0.f};

    const float* mp = g_mem + (size_t)bh * D_ * D_;

    for (int kc = 0; kc < D_; kc += 16) {
#pragma unroll
        for (int i = 0; i < 2; i++) {
            int slot = tid + i * 256;
            int r = slot >> 5;
            int c = (slot & 31) << 2;
            *(float4*)&sM[r][c] = *(const float4*)(mp + (size_t)(kc + r) * D_ + c);
        }
        __syncthreads();

#pragma unroll
        for (int kk = 0; kk < 16; kk++) {
            ulonglong2 b01 = *(const ulonglong2*)&sM[kk][v0];
            ulonglong2 b23 = *(const ulonglong2*)&sM[kk][v0 + 4];
            unsigned long long Bp[4] = { b01.x, b01.y, b23.x, b23.y };
            float nk = sN[kc + kk];
#pragma unroll
            for (int i = 0; i < 4; i++) {
                float ai = sQ[sl0 + i][kc + kk];
                unsigned long long ad = fdup(ai);
#pragma unroll
                for (int j = 0; j < 4; j++) ffma2(acc[i][j], ad, Bp[j]);
                dacc[i] += ai * nk;
            }
        }
        __syncthreads();
    }

    float bf = bal[h];
    float gw = 1.f / (1.f + __expf(-bf));
    float lw = 1.f / (1.f + __expf(-(1.f - bf)));

    const float* lp = Lin + (size_t)bh * S_ * D_ + (size_t)s0 * D_;
    __half* op = g_attn + (size_t)(b * S_ + s0) * DM_ + (size_t)h * D_;

#pragma unroll
    for (int i = 0; i < 4; i++) {
        float r[8];
#pragma unroll
        for (int j = 0; j < 4; j++) {
            float2 v = f2unpack(acc[i][j]);
            r[2 * j] = v.x; r[2 * j + 1] = v.y;
        }
        float rd = gw / dacc[i];
        int sl = sl0 + i;
        float4 l0 = *(const float4*)(lp + (size_t)sl * D_ + v0);
        float4 l1 = *(const float4*)(lp + (size_t)sl * D_ + v0 + 4);
        uint4 hv;
        hv.x = h2pack(r[0] * rd + lw * l0.x, r[1] * rd + lw * l0.y);
        hv.y = h2pack(r[2] * rd + lw * l0.z, r[3] * rd + lw * l0.w);
        hv.z = h2pack(r[4] * rd + lw * l1.x, r[5] * rd + lw * l1.y);
        hv.w = h2pack(r[6] * rd + lw * l1.z, r[7] * rd + lw * l1.w);
        *(uint4*)(op + (size_t)sl * DM_ + v0) = hv;
    }
}

// ---------------------------------------------------------------------------
// Kernel 3: Out[m,n] = sum_k attn[m,k] * w_o[n,k]
// fp16 mma.sync m16n8k16, single pass. Block tile 256x128, BK=32,
// cp.async double buffer, 8 warps (4m x 2n) of 64x64.
// ---------------------------------------------------------------------------
#define BM_ 256
#define BN_ 128
#define BK_ 32
#define STRD_B_ 80                           // padded row stride in BYTES (40 fp16)
#define A_TILE_B_ (BM_ * STRD_B_)            // 20480
#define B_TILE_B_ (BN_ * STRD_B_)            // 10240
#define PBUF_ (A_TILE_B_ + B_TILE_B_)        // 30720
#define PSMEM_ (2 * PBUF_)                   // 61440

__global__ __launch_bounds__(256, 1) void k_proj_mma(float* __restrict__ Out)
{
    extern __shared__ char smem[];
    const uint32_t sbase = s2u(smem);
    const int tid  = threadIdx.x;
    const int lane = tid & 31;
    const int wid  = tid >> 5;
    const int wm   = wid >> 1;               // 0..3
    const int wn   = wid & 1;                // 0..1
    const int m0   = blockIdx.y * BM_;
    const int n0   = blockIdx.x * BN_;

    const __half* Ap = g_attn + (size_t)m0 * DM_;
    const __half* Bw = g_wo   + (size_t)n0 * DM_;

    float acc[4][8][4];
#pragma unroll
    for (int i = 0; i < 4; i++)
#pragma unroll
        for (int j = 0; j < 8; j++)
#pragma unroll
            for (int q = 0; q < 4; q++) acc[i][j][q] = 0.f;

    // per-thread load slots (4 threads x 16B cover one 64B row of BK=32 fp16)
    const int lr = tid >> 2;                 // 0..63
    const int lc = (tid & 3) * 8;            // k-element offset of 16B chunk

    // ldmatrix fragment addresses (within a buffer)
    const uint32_t aFragOff =
        (uint32_t)(wm * 64 + (lane & 15)) * STRD_B_ + ((lane >> 4) << 4);
    const uint32_t bFragOff =
        (uint32_t)(wn * 64 + (lane & 7) + ((lane >> 4) << 3)) * STRD_B_ +
        ((lane & 8) << 1);

    auto load_tiles = [&](int bsel, int k0) {
        const uint32_t sb = sbase + (uint32_t)bsel * PBUF_;
#pragma unroll
        for (int i = 0; i < 4; i++) {        // A: 256 rows
            int r = lr + i * 64;
            size_t go = (size_t)r * DM_ + k0 + lc;
            uint32_t so = (uint32_t)r * STRD_B_ + (uint32_t)(tid & 3) * 16;
            cp16(sb + so, Ap + go);
        }
#pragma unroll
        for (int i = 0; i < 2; i++) {        // B: 128 rows
            int r = lr + i * 64;
            size_t go = (size_t)r * DM_ + k0 + lc;
            uint32_t so = (uint32_t)r * STRD_B_ + (uint32_t)(tid & 3) * 16;
            cp16(sb + A_TILE_B_ + so, Bw + go);
        }
    };

    load_tiles(0, 0);   CP_COMMIT();
    load_tiles(1, BK_); CP_COMMIT();

    for (int it = 0; it < DM_ / BK_; it++) {
        CP_WAIT1();
        __syncthreads();
        const uint32_t sb = sbase + (uint32_t)(it & 1) * PBUF_;

#pragma unroll
        for (int ks = 0; ks < 2; ks++) {
            uint32_t ah[4][4], bw[4][4];
#pragma unroll
            for (int mt = 0; mt < 4; mt++) {
                uint32_t a = sb + aFragOff + (uint32_t)mt * (16 * STRD_B_) + ks * 32;
                ldx4(ah[mt], a);
            }
#pragma unroll
            for (int p = 0; p < 4; p++) {
                uint32_t a = sb + A_TILE_B_ + bFragOff +
                             (uint32_t)p * (16 * STRD_B_) + ks * 32;
                ldx4(bw[p], a);
            }
#pragma unroll
            for (int mt = 0; mt < 4; mt++) {
#pragma unroll
                for (int p = 0; p < 4; p++) {
                    mma16816(acc[mt][2 * p],     ah[mt], bw[p][0], bw[p][1]);
                    mma16816(acc[mt][2 * p + 1], ah[mt], bw[p][2], bw[p][3]);
                }
            }
        }
        __syncthreads();
        if (it + 2 < DM_ / BK_) load_tiles(it & 1, (it + 2) * BK_);
        CP_COMMIT();
    }

    // ---- epilogue ----
#pragma unroll
    for (int mt = 0; mt < 4; mt++) {
        int r0 = m0 + wm * 64 + mt * 16 + (lane >> 2);
#pragma unroll
        for (int nt = 0; nt < 8; nt++) {
            int col = n0 + wn * 64 + nt * 8 + (lane & 3) * 2;
            float* p0 = Out + (size_t)r0 * DM_ + col;
            *(float2*)p0              = make_float2(acc[mt][nt][0], acc[mt][nt][1]);
            *(float2*)(p0 + 8 * DM_)  = make_float2(acc[mt][nt][2], acc[mt][nt][3]);
        }
    }
}

// ---------------------------------------------------------------------------
// kernel_launch
// inputs: 0=query, 1=key, 2=value, 3=local_attn_outputs, 4=balance, 5=w_o
// ---------------------------------------------------------------------------
extern "C" void kernel_launch(void* const* d_in, const int* in_sizes, int n_in,
                              void* d_out, int out_size)
{
    const float* Q   = (const float*)d_in[0];
    const float* K   = (const float*)d_in[1];
    const float* V   = (const float*)d_in[2];
    const float* L   = (const float*)d_in[3];
    const float* bal = (const float*)d_in[4];
    const float* Wo  = (const float*)d_in[5];
    float* out = (float*)d_out;

    cudaFuncSetAttribute(k_proj_mma, cudaFuncAttributeMaxDynamicSharedMemorySize, PSMEM_);

    k_cvt<<<(DM_ * DM_) / 4 / 256, 256>>>(Wo);

    dim3 g1(BH_, SPLIT_);
    k_memory<<<g1, 256>>>(K, V);
    k_mreduce<<<BH_ * D_ * D_ / 4 / 256, 256>>>();

    dim3 g2(S_ / 64, BH_);
    k_retrieve<<<g2, 256>>>(Q, L, bal);

    dim3 g3(DM_ / BN_, M_ / BM_);     // 32 x 32
    k_proj_mma<<<g3, 256, PSMEM_>>>(out);
}

// round 15
// speedup vs baseline: 4.8885x; 1.2340x over previous
#include <cuda_runtime.h>
#include <cuda_fp16.h>
#include <cstdint>

// Problem constants
#define B_  4
#define H_  32
#define S_  2048
#define D_  128
#define BH_ (B_ * H_)          // 128
#define DM_ (H_ * D_)          // 4096
#define M_  (B_ * S_)          // 8192

#define SPLIT_ 8
#define SC_ (S_ / SPLIT_)      // 256

// Scratch (device globals: no allocation allowed in kernel_launch)
__device__ float g_mem_p[SPLIT_ * BH_ * D_ * D_];            // partials       64 MB
__device__ float g_nrm_p[SPLIT_ * BH_ * D_];                 // partial norms
__device__ __half g_mem_th[(size_t)BH_ * D_ * D_];           // mem^T hi fp16   4 MB
__device__ __half g_mem_tl[(size_t)BH_ * D_ * D_];           // mem^T lo fp16   4 MB
__device__ __half g_attn[(size_t)M_ * DM_];                  // attn fp16      64 MB
__device__ __half g_wo[(size_t)DM_ * DM_];                   // w_o fp16       32 MB

// ---------------------------------------------------------------------------
// helpers
// ---------------------------------------------------------------------------
__device__ __forceinline__ float phi1(float x) {
    return x > 0.f ? x + 1.f : __expf(x);
}
__device__ __forceinline__ unsigned long long fdup(float x) {
    unsigned long long r;
    asm("mov.b64 %0, {%1, %2};" : "=l"(r) : "f"(x), "f"(x));
    return r;
}
__device__ __forceinline__ void ffma2(unsigned long long& acc,
                                      unsigned long long a,
                                      unsigned long long b) {
    asm("fma.rn.f32x2 %0, %1, %2, %0;" : "+l"(acc) : "l"(a), "l"(b));
}
__device__ __forceinline__ float2 f2unpack(unsigned long long v) {
    float2 r;
    asm("mov.b64 {%0, %1}, %2;" : "=f"(r.x), "=f"(r.y) : "l"(v));
    return r;
}
__device__ __forceinline__ uint32_t h2pack(float a, float b) {
    __half2 t = __floats2half2_rn(a, b);
    return *reinterpret_cast<uint32_t*>(&t);
}
__device__ __forceinline__ uint32_t s2u(const void* p) {
    uint32_t r;
    asm("{ .reg .u64 t; cvta.to.shared.u64 t, %1; cvt.u32.u64 %0, t; }" : "=r"(r) : "l"(p));
    return r;
}
__device__ __forceinline__ void cp16(uint32_t s, const void* g) {
    asm volatile("cp.async.cg.shared.global [%0], [%1], 16;" :: "r"(s), "l"(g) : "memory");
}
#define CP_COMMIT() asm volatile("cp.async.commit_group;" ::: "memory")
#define CP_WAIT2()  asm volatile("cp.async.wait_group 2;" ::: "memory")

__device__ __forceinline__ void ldx4(uint32_t* r, uint32_t a) {
    asm volatile("ldmatrix.sync.aligned.m8n8.x4.shared.b16 {%0,%1,%2,%3}, [%4];"
                 : "=r"(r[0]), "=r"(r[1]), "=r"(r[2]), "=r"(r[3]) : "r"(a));
}
__device__ __forceinline__ void mma16816(float* c, const uint32_t* a,
                                         uint32_t b0, uint32_t b1) {
    asm volatile(
        "mma.sync.aligned.m16n8k16.row.col.f32.f16.f16.f32 "
        "{%0,%1,%2,%3}, {%4,%5,%6,%7}, {%8,%9}, {%0,%1,%2,%3};"
        : "+f"(c[0]), "+f"(c[1]), "+f"(c[2]), "+f"(c[3])
        : "r"(a[0]), "r"(a[1]), "r"(a[2]), "r"(a[3]), "r"(b0), "r"(b1));
}

// ---------------------------------------------------------------------------
// Kernel 0: w_o -> fp16
// ---------------------------------------------------------------------------
__global__ __launch_bounds__(256) void k_cvt(const float* __restrict__ Wo) {
    size_t i = (size_t)blockIdx.x * 256 + threadIdx.x;   // float4 index
    float4 w = ((const float4*)Wo)[i];
    uint2 hp;
    hp.x = h2pack(w.x, w.y);
    hp.y = h2pack(w.z, w.w);
    ((uint2*)g_wo)[i] = hp;
}

// ---------------------------------------------------------------------------
// Kernel 1: partial memory[chunk][bh] = phiK^T @ V over S-chunk + norm partials
// (FFMA2 fp32 — exact)
// ---------------------------------------------------------------------------
__global__ __launch_bounds__(256) void k_memory(const float* __restrict__ Kin,
                                                const float* __restrict__ Vin)
{
    __shared__ float sK[16][128];
    __shared__ float sV[16][128];

    const int bh    = blockIdx.x;
    const int chunk = blockIdx.y;
    const float* Kp = Kin + (size_t)bh * S_ * D_ + (size_t)chunk * SC_ * D_;
    const float* Vp = Vin + (size_t)bh * S_ * D_ + (size_t)chunk * SC_ * D_;
    const int tid = threadIdx.x;
    const int tx  = tid & 15, ty = tid >> 4;
    const int k0  = ty * 8,  v0 = tx * 8;

    unsigned long long acc[8][4];
#pragma unroll
    for (int i = 0; i < 8; i++)
#pragma unroll
        for (int j = 0; j < 4; j++) acc[i][j] = 0ULL;
    float nacc = 0.f;

    for (int s0 = 0; s0 < SC_; s0 += 16) {
#pragma unroll
        for (int i = 0; i < 2; i++) {
            int slot = tid + i * 256;
            int r = slot >> 5;
            int c = (slot & 31) << 2;
            float4 kv = *(const float4*)(Kp + (size_t)(s0 + r) * D_ + c);
            kv.x = phi1(kv.x); kv.y = phi1(kv.y);
            kv.z = phi1(kv.z); kv.w = phi1(kv.w);
            *(float4*)&sK[r][c] = kv;
            *(float4*)&sV[r][c] = *(const float4*)(Vp + (size_t)(s0 + r) * D_ + c);
        }
        __syncthreads();

        if (tid < 128) {
#pragma unroll
            for (int r = 0; r < 16; r++) nacc += sK[r][tid];
        }

#pragma unroll
        for (int r = 0; r < 16; r++) {
            float a[8];
            *(float4*)&a[0] = *(float4*)&sK[r][k0];
            *(float4*)&a[4] = *(float4*)&sK[r][k0 + 4];
            ulonglong2 b01 = *(const ulonglong2*)&sV[r][v0];
            ulonglong2 b23 = *(const ulonglong2*)&sV[r][v0 + 4];
            unsigned long long Bp[4] = { b01.x, b01.y, b23.x, b23.y };
#pragma unroll
            for (int i = 0; i < 8; i++) {
                unsigned long long ad = fdup(a[i]);
#pragma unroll
                for (int j = 0; j < 4; j++) ffma2(acc[i][j], ad, Bp[j]);
            }
        }
        __syncthreads();
    }

    float* mp = g_mem_p + ((size_t)chunk * BH_ + bh) * D_ * D_;
#pragma unroll
    for (int i = 0; i < 8; i++) {
        float o[8];
#pragma unroll
        for (int j = 0; j < 4; j++) {
            float2 v = f2unpack(acc[i][j]);
            o[2 * j] = v.x; o[2 * j + 1] = v.y;
        }
        *(float4*)(mp + (size_t)(k0 + i) * D_ + v0)     = *(float4*)&o[0];
        *(float4*)(mp + (size_t)(k0 + i) * D_ + v0 + 4) = *(float4*)&o[4];
    }
    if (tid < 128) g_nrm_p[(chunk * BH_ + bh) * D_ + tid] = nacc;
}

// ---------------------------------------------------------------------------
// Kernel 1b: reduce SPLIT_ partials, emit TRANSPOSED fp16 hi/lo memory [v][k]
// one block per bh; dynamic smem 128x129 fp32
// ---------------------------------------------------------------------------
#define MR_SMEM_ (128 * 129 * 4)
__global__ __launch_bounds__(256) void k_mreduce() {
    extern __shared__ float sT[];                 // [128][129]
    const int bh  = blockIdx.x;
    const int tid = threadIdx.x;

    for (int i = 0; i < 16; i++) {
        int e4 = tid + i * 256;                   // float4 index (4096 total)
        float4 s = make_float4(0.f, 0.f, 0.f, 0.f);
#pragma unroll
        for (int c = 0; c < SPLIT_; c++) {
            const float4* p = (const float4*)(g_mem_p + ((size_t)(c * BH_ + bh) << 14));
            float4 t = p[e4];
            s.x += t.x; s.y += t.y; s.z += t.z; s.w += t.w;
        }
        int k = e4 >> 5;
        int v = (e4 & 31) * 4;
        sT[k * 129 + v + 0] = s.x;
        sT[k * 129 + v + 1] = s.y;
        sT[k * 129 + v + 2] = s.z;
        sT[k * 129 + v + 3] = s.w;
    }
    __syncthreads();

    uint32_t* th = (uint32_t*)(g_mem_th + (size_t)bh * D_ * D_);
    uint32_t* tl = (uint32_t*)(g_mem_tl + (size_t)bh * D_ * D_);
    for (int i = 0; i < 32; i++) {
        int e2 = tid + i * 256;                   // half2 index (8192 total)
        int v = e2 >> 6, k = (e2 & 63) * 2;
        float x0 = sT[(k + 0) * 129 + v];
        float x1 = sT[(k + 1) * 129 + v];
        float h0 = __half2float(__float2half_rn(x0));
        float h1 = __half2float(__float2half_rn(x1));
        th[e2] = h2pack(x0, x1);
        tl[e2] = h2pack(x0 - h0, x1 - h1);
    }
}

// ---------------------------------------------------------------------------
// Kernel 2: retrieved = phiQ @ memory via HMMA (B = mem^T hi/lo, 2-pass),
//           denom from the SAME fp16 phiQ, gated combine, fp16 out [b,s,h*D+d]
// block = (s-tile 128, bh); 8 warps, warp tile 64(s) x 32(v)
// ---------------------------------------------------------------------------
#define RSTR_ 272                                 // 128 fp16 + 16B pad
#define R_OFF_MH (128 * RSTR_)                    // 34816
#define R_OFF_ML (2 * 128 * RSTR_)                // 69632
#define R_OFF_N  (3 * 128 * RSTR_)                // 104448
#define R_OFF_D  (R_OFF_N + 512)                  // 104960
#define RSMEM_   (R_OFF_D + 512)                  // 105472

__global__ __launch_bounds__(256, 1) void k_retr_mma(const float* __restrict__ Qin,
                                                     const float* __restrict__ Lin,
                                                     const float* __restrict__ bal)
{
    extern __shared__ char smem[];
    const uint32_t sb = s2u(smem);
    const int tid  = threadIdx.x;
    const int lane = tid & 31;
    const int wid  = tid >> 5;
    const int wm   = wid >> 2;                    // 0..1  (64 rows each)
    const int wn   = wid & 3;                     // 0..3  (32 cols each)
    const int bh   = blockIdx.y;
    const int s0   = blockIdx.x * 128;
    const int h    = bh & (H_ - 1);
    const int b    = bh >> 5;

    // --- load Q tile (fp32 -> phi -> fp16 smem) ---
    const float* Qp = Qin + (size_t)bh * S_ * D_ + (size_t)s0 * D_;
#pragma unroll
    for (int i = 0; i < 16; i++) {
        int u = tid + i * 256;                    // float4 idx, 4096 total
        int r = u >> 5;
        int c = (u & 31) * 4;
        float4 q = *(const float4*)(Qp + (size_t)r * D_ + c);
        q.x = phi1(q.x); q.y = phi1(q.y);
        q.z = phi1(q.z); q.w = phi1(q.w);
        uint32_t* d = (uint32_t*)(smem + r * RSTR_ + c * 2);
        d[0] = h2pack(q.x, q.y);
        d[1] = h2pack(q.z, q.w);
    }
    // --- load mem^T hi/lo tiles ---
    {
        const uint4* mh = (const uint4*)(g_mem_th + (size_t)bh * D_ * D_);
        const uint4* ml = (const uint4*)(g_mem_tl + (size_t)bh * D_ * D_);
#pragma unroll
        for (int i = 0; i < 8; i++) {
            int u = tid + i * 256;                // 16B chunk idx, 2048 total
            int r = u >> 4, cc = u & 15;
            *(uint4*)(smem + R_OFF_MH + r * RSTR_ + cc * 16) = mh[u];
            *(uint4*)(smem + R_OFF_ML + r * RSTR_ + cc * 16) = ml[u];
        }
    }
    if (tid < 128) {
        float s = 0.f;
#pragma unroll
        for (int c = 0; c < SPLIT_; c++) s += g_nrm_p[(c * BH_ + bh) * D_ + tid];
        ((float*)(smem + R_OFF_N))[tid] = s;
    }
    __syncthreads();

    // --- denom[s] from the same fp16 phiQ (consistent with numerator) ---
    {
        int row = tid >> 1, half = tid & 1;
        const __half* qr = (const __half*)(smem + row * RSTR_) + half * 64;
        const float*  nn = (const float*)(smem + R_OFF_N) + half * 64;
        float s = 0.f;
#pragma unroll
        for (int k = 0; k < 64; k++) s += __half2float(qr[k]) * nn[k];
        s += __shfl_xor_sync(0xFFFFFFFFu, s, 1);
        if (!half) ((float*)(smem + R_OFF_D))[row] = s;
    }
    __syncthreads();

    // --- HMMA: 64x32 per warp, K=128, 2-pass (hi, lo) ---
    float acc[4][4][4];
#pragma unroll
    for (int i = 0; i < 4; i++)
#pragma unroll
        for (int j = 0; j < 4; j++)
#pragma unroll
            for (int q = 0; q < 4; q++) acc[i][j][q] = 0.f;

    const uint32_t aOff = (uint32_t)(wm * 64 + (lane & 15)) * RSTR_ + ((lane >> 4) << 4);
    const uint32_t bOff = (uint32_t)(wn * 32 + (lane & 7) + ((lane >> 4) << 3)) * RSTR_ +
                          ((lane & 8) << 1);

#pragma unroll
    for (int ks = 0; ks < 8; ks++) {
        uint32_t af[4][4], bh_[2][4], bl_[2][4];
#pragma unroll
        for (int mt = 0; mt < 4; mt++)
            ldx4(af[mt], sb + aOff + (uint32_t)mt * (16 * RSTR_) + ks * 32);
#pragma unroll
        for (int p = 0; p < 2; p++) {
            uint32_t a = sb + bOff + (uint32_t)p * (16 * RSTR_) + ks * 32;
            ldx4(bh_[p], a + R_OFF_MH);
            ldx4(bl_[p], a + R_OFF_ML);
        }
#pragma unroll
        for (int mt = 0; mt < 4; mt++)
#pragma unroll
            for (int p = 0; p < 2; p++) {
                mma16816(acc[mt][2 * p],     af[mt], bh_[p][0], bh_[p][1]);
                mma16816(acc[mt][2 * p + 1], af[mt], bh_[p][2], bh_[p][3]);
            }
#pragma unroll
        for (int mt = 0; mt < 4; mt++)
#pragma unroll
            for (int p = 0; p < 2; p++) {
                mma16816(acc[mt][2 * p],     af[mt], bl_[p][0], bl_[p][1]);
                mma16816(acc[mt][2 * p + 1], af[mt], bl_[p][2], bl_[p][3]);
            }
    }

    // --- epilogue: gate + combine with local, store fp16 to g_attn ---
    float bf = bal[h];
    float gw = 1.f / (1.f + __expf(-bf));
    float lw = 1.f / (1.f + __expf(-(1.f - bf)));

    const float* lp = Lin + (size_t)bh * S_ * D_ + (size_t)s0 * D_;
    __half* op = g_attn + (size_t)(b * S_ + s0) * DM_ + (size_t)h * D_;
    const float* sDen = (const float*)(smem + R_OFF_D);

#pragma unroll
    for (int mt = 0; mt < 4; mt++) {
        int r0 = wm * 64 + mt * 16 + (lane >> 2);
        float rd0 = gw / sDen[r0];
        float rd1 = gw / sDen[r0 + 8];
#pragma unroll
        for (int nt = 0; nt < 4; nt++) {
            int col = wn * 32 + nt * 8 + (lane & 3) * 2;
            float2 l0 = *(const float2*)(lp + (size_t)r0 * D_ + col);
            float2 l1 = *(const float2*)(lp + (size_t)(r0 + 8) * D_ + col);
            *(uint32_t*)(op + (size_t)r0 * DM_ + col) =
                h2pack(acc[mt][nt][0] * rd0 + lw * l0.x,
                       acc[mt][nt][1] * rd0 + lw * l0.y);
            *(uint32_t*)(op + (size_t)(r0 + 8) * DM_ + col) =
                h2pack(acc[mt][nt][2] * rd1 + lw * l1.x,
                       acc[mt][nt][3] * rd1 + lw * l1.y);
        }
    }
}

// ---------------------------------------------------------------------------
// Kernel 3: Out[m,n] = sum_k attn[m,k] * w_o[n,k]
// fp16 mma.sync m16n8k16, single pass. Block tile 256x128, BK=64,
// 3-stage cp.async pipeline, 8 warps (4m x 2n) of 64x64.
// ---------------------------------------------------------------------------
#define BM_ 256
#define BN_ 128
#define BK_ 64
#define PSTR_ 144                            // 64 fp16 = 128B + 16B pad
#define A_TILE_B_ (BM_ * PSTR_)              // 36864
#define B_TILE_B_ (BN_ * PSTR_)              // 18432
#define PBUF_ (A_TILE_B_ + B_TILE_B_)        // 55296
#define NSTG_ 3
#define PSMEM_ (NSTG_ * PBUF_)               // 165888
#define NIT_ (DM_ / BK_)                     // 64

__global__ __launch_bounds__(256, 1) void k_proj_mma(float* __restrict__ Out)
{
    extern __shared__ char smem[];
    const uint32_t sbase = s2u(smem);
    const int tid  = threadIdx.x;
    const int lane = tid & 31;
    const int wid  = tid >> 5;
    const int wm   = wid >> 1;               // 0..3
    const int wn   = wid & 1;                // 0..1
    const int m0   = blockIdx.y * BM_;
    const int n0   = blockIdx.x * BN_;

    const __half* Ap = g_attn + (size_t)m0 * DM_;
    const __half* Bw = g_wo   + (size_t)n0 * DM_;

    float acc[4][8][4];
#pragma unroll
    for (int i = 0; i < 4; i++)
#pragma unroll
        for (int j = 0; j < 8; j++)
#pragma unroll
            for (int q = 0; q < 4; q++) acc[i][j][q] = 0.f;

    const uint32_t aFragOff =
        (uint32_t)(wm * 64 + (lane & 15)) * PSTR_ + ((lane >> 4) << 4);
    const uint32_t bFragOff =
        (uint32_t)(wn * 64 + (lane & 7) + ((lane >> 4) << 3)) * PSTR_ +
        ((lane & 8) << 1);

    auto load_tiles = [&](int bsel, int k0) {
        const uint32_t sbuf = sbase + (uint32_t)bsel * PBUF_;
#pragma unroll
        for (int i = 0; i < 8; i++) {        // A: 256 rows x 64 fp16 = 2048 chunks
            int u = tid + i * 256;
            int r = u >> 3, ch = u & 7;
            cp16(sbuf + (uint32_t)r * PSTR_ + ch * 16,
                 Ap + (size_t)r * DM_ + k0 + ch * 8);
        }
#pragma unroll
        for (int i = 0; i < 4; i++) {        // B: 128 rows = 1024 chunks
            int u = tid + i * 256;
            int r = u >> 3, ch = u & 7;
            cp16(sbuf + A_TILE_B_ + (uint32_t)r * PSTR_ + ch * 16,
                 Bw + (size_t)r * DM_ + k0 + ch * 8);
        }
    };

    load_tiles(0, 0);       CP_COMMIT();
    load_tiles(1, BK_);     CP_COMMIT();
    load_tiles(2, 2 * BK_); CP_COMMIT();

    int cur = 0;
    for (int it = 0; it < NIT_; it++) {
        CP_WAIT2();                           // oldest of 3 pending done
        __syncthreads();
        const uint32_t sbuf = sbase + (uint32_t)cur * PBUF_;

#pragma unroll
        for (int ks = 0; ks < 4; ks++) {
            uint32_t ah[4][4], bw[4][4];
#pragma unroll
            for (int mt = 0; mt < 4; mt++)
                ldx4(ah[mt], sbuf + aFragOff + (uint32_t)mt * (16 * PSTR_) + ks * 32);
#pragma unroll
            for (int p = 0; p < 4; p++)
                ldx4(bw[p], sbuf + A_TILE_B_ + bFragOff +
                             (uint32_t)p * (16 * PSTR_) + ks * 32);
#pragma unroll
            for (int mt = 0; mt < 4; mt++)
#pragma unroll
                for (int p = 0; p < 4; p++) {
                    mma16816(acc[mt][2 * p],     ah[mt], bw[p][0], bw[p][1]);
                    mma16816(acc[mt][2 * p + 1], ah[mt], bw[p][2], bw[p][3]);
                }
        }
        __syncthreads();
        if (it + 3 < NIT_) load_tiles(cur, (it + 3) * BK_);
        CP_COMMIT();
        cur = (cur == 2) ? 0 : cur + 1;
    }

    // ---- epilogue ----
#pragma unroll
    for (int mt = 0; mt < 4; mt++) {
        int r0 = m0 + wm * 64 + mt * 16 + (lane >> 2);
#pragma unroll
        for (int nt = 0; nt < 8; nt++) {
            int col = n0 + wn * 64 + nt * 8 + (lane & 3) * 2;
            float* p0 = Out + (size_t)r0 * DM_ + col;
            *(float2*)p0              = make_float2(acc[mt][nt][0], acc[mt][nt][1]);
            *(float2*)(p0 + 8 * DM_)  = make_float2(acc[mt][nt][2], acc[mt][nt][3]);
        }
    }
}

// ---------------------------------------------------------------------------
// kernel_launch
// inputs: 0=query, 1=key, 2=value, 3=local_attn_outputs, 4=balance, 5=w_o
// ---------------------------------------------------------------------------
extern "C" void kernel_launch(void* const* d_in, const int* in_sizes, int n_in,
                              void* d_out, int out_size)
{
    const float* Q   = (const float*)d_in[0];
    const float* K   = (const float*)d_in[1];
    const float* V   = (const float*)d_in[2];
    const float* L   = (const float*)d_in[3];
    const float* bal = (const float*)d_in[4];
    const float* Wo  = (const float*)d_in[5];
    float* out = (float*)d_out;

    cudaFuncSetAttribute(k_mreduce,  cudaFuncAttributeMaxDynamicSharedMemorySize, MR_SMEM_);
    cudaFuncSetAttribute(k_retr_mma, cudaFuncAttributeMaxDynamicSharedMemorySize, RSMEM_);
    cudaFuncSetAttribute(k_proj_mma, cudaFuncAttributeMaxDynamicSharedMemorySize, PSMEM_);

    k_cvt<<<(DM_ * DM_) / 4 / 256, 256>>>(Wo);

    dim3 g1(BH_, SPLIT_);
    k_memory<<<g1, 256>>>(K, V);
    k_mreduce<<<BH_, 256, MR_SMEM_>>>();

    dim3 g2(S_ / 128, BH_);
    k_retr_mma<<<g2, 256, RSMEM_>>>(Q, L, bal);

    dim3 g3(DM_ / BN_, M_ / BM_);     // 32 x 32
    k_proj_mma<<<g3, 256, PSMEM_>>>(out);
}

// round 16
// speedup vs baseline: 5.1016x; 1.0436x over previous
#include <cuda_runtime.h>
#include <cuda_fp16.h>
#include <cstdint>

// Problem constants
#define B_  4
#define H_  32
#define S_  2048
#define D_  128
#define BH_ (B_ * H_)          // 128
#define DM_ (H_ * D_)          // 4096
#define M_  (B_ * S_)          // 8192

#define SPLIT_ 8
#define SC_ (S_ / SPLIT_)      // 256

// Scratch (device globals: no allocation allowed in kernel_launch)
__device__ float g_mem_p[SPLIT_ * BH_ * D_ * D_];            // partials       64 MB
__device__ float g_nrm_p[SPLIT_ * BH_ * D_];                 // partial norms
__device__ __half g_mem_th[(size_t)BH_ * D_ * D_];           // mem^T fp16      4 MB
__device__ __half g_attn[(size_t)M_ * DM_];                  // attn fp16      64 MB
__device__ __half g_wo[(size_t)DM_ * DM_];                   // w_o fp16       32 MB

// ---------------------------------------------------------------------------
// helpers
// ---------------------------------------------------------------------------
__device__ __forceinline__ float phi1(float x) {
    return x > 0.f ? x + 1.f : __expf(x);
}
__device__ __forceinline__ unsigned long long fdup(float x) {
    unsigned long long r;
    asm("mov.b64 %0, {%1, %2};" : "=l"(r) : "f"(x), "f"(x));
    return r;
}
__device__ __forceinline__ void ffma2(unsigned long long& acc,
                                      unsigned long long a,
                                      unsigned long long b) {
    asm("fma.rn.f32x2 %0, %1, %2, %0;" : "+l"(acc) : "l"(a), "l"(b));
}
__device__ __forceinline__ float2 f2unpack(unsigned long long v) {
    float2 r;
    asm("mov.b64 {%0, %1}, %2;" : "=f"(r.x), "=f"(r.y) : "l"(v));
    return r;
}
__device__ __forceinline__ uint32_t h2pack(float a, float b) {
    __half2 t = __floats2half2_rn(a, b);
    return *reinterpret_cast<uint32_t*>(&t);
}
__device__ __forceinline__ uint32_t s2u(const void* p) {
    uint32_t r;
    asm("{ .reg .u64 t; cvta.to.shared.u64 t, %1; cvt.u32.u64 %0, t; }" : "=r"(r) : "l"(p));
    return r;
}
__device__ __forceinline__ void cp16(uint32_t s, const void* g) {
    asm volatile("cp.async.cg.shared.global [%0], [%1], 16;" :: "r"(s), "l"(g) : "memory");
}
#define CP_COMMIT() asm volatile("cp.async.commit_group;" ::: "memory")
#define CP_WAIT(n)  asm volatile("cp.async.wait_group %0;" :: "n"(n) : "memory")

__device__ __forceinline__ void ldx4(uint32_t* r, uint32_t a) {
    asm volatile("ldmatrix.sync.aligned.m8n8.x4.shared.b16 {%0,%1,%2,%3}, [%4];"
                 : "=r"(r[0]), "=r"(r[1]), "=r"(r[2]), "=r"(r[3]) : "r"(a));
}
__device__ __forceinline__ void mma16816(float* c, const uint32_t* a,
                                         uint32_t b0, uint32_t b1) {
    asm volatile(
        "mma.sync.aligned.m16n8k16.row.col.f32.f16.f16.f32 "
        "{%0,%1,%2,%3}, {%4,%5,%6,%7}, {%8,%9}, {%0,%1,%2,%3};"
        : "+f"(c[0]), "+f"(c[1]), "+f"(c[2]), "+f"(c[3])
        : "r"(a[0]), "r"(a[1]), "r"(a[2]), "r"(a[3]), "r"(b0), "r"(b1));
}

// ---------------------------------------------------------------------------
// Kernel 0: w_o -> fp16
// ---------------------------------------------------------------------------
__global__ __launch_bounds__(256) void k_cvt(const float* __restrict__ Wo) {
    size_t i = (size_t)blockIdx.x * 256 + threadIdx.x;   // float4 index
    float4 w = ((const float4*)Wo)[i];
    uint2 hp;
    hp.x = h2pack(w.x, w.y);
    hp.y = h2pack(w.z, w.w);
    ((uint2*)g_wo)[i] = hp;
}

// ---------------------------------------------------------------------------
// Kernel 1: partial memory[chunk][bh] = phiK^T @ V over S-chunk + norm partials
// (FFMA2 fp32 — exact)
// ---------------------------------------------------------------------------
__global__ __launch_bounds__(256) void k_memory(const float* __restrict__ Kin,
                                                const float* __restrict__ Vin)
{
    __shared__ float sK[16][128];
    __shared__ float sV[16][128];

    const int bh    = blockIdx.x;
    const int chunk = blockIdx.y;
    const float* Kp = Kin + (size_t)bh * S_ * D_ + (size_t)chunk * SC_ * D_;
    const float* Vp = Vin + (size_t)bh * S_ * D_ + (size_t)chunk * SC_ * D_;
    const int tid = threadIdx.x;
    const int tx  = tid & 15, ty = tid >> 4;
    const int k0  = ty * 8,  v0 = tx * 8;

    unsigned long long acc[8][4];
#pragma unroll
    for (int i = 0; i < 8; i++)
#pragma unroll
        for (int j = 0; j < 4; j++) acc[i][j] = 0ULL;
    float nacc = 0.f;

    for (int s0 = 0; s0 < SC_; s0 += 16) {
#pragma unroll
        for (int i = 0; i < 2; i++) {
            int slot = tid + i * 256;
            int r = slot >> 5;
            int c = (slot & 31) << 2;
            float4 kv = *(const float4*)(Kp + (size_t)(s0 + r) * D_ + c);
            kv.x = phi1(kv.x); kv.y = phi1(kv.y);
            kv.z = phi1(kv.z); kv.w = phi1(kv.w);
            *(float4*)&sK[r][c] = kv;
            *(float4*)&sV[r][c] = *(const float4*)(Vp + (size_t)(s0 + r) * D_ + c);
        }
        __syncthreads();

        if (tid < 128) {
#pragma unroll
            for (int r = 0; r < 16; r++) nacc += sK[r][tid];
        }

#pragma unroll
        for (int r = 0; r < 16; r++) {
            float a[8];
            *(float4*)&a[0] = *(float4*)&sK[r][k0];
            *(float4*)&a[4] = *(float4*)&sK[r][k0 + 4];
            ulonglong2 b01 = *(const ulonglong2*)&sV[r][v0];
            ulonglong2 b23 = *(const ulonglong2*)&sV[r][v0 + 4];
            unsigned long long Bp[4] = { b01.x, b01.y, b23.x, b23.y };
#pragma unroll
            for (int i = 0; i < 8; i++) {
                unsigned long long ad = fdup(a[i]);
#pragma unroll
                for (int j = 0; j < 4; j++) ffma2(acc[i][j], ad, Bp[j]);
            }
        }
        __syncthreads();
    }

    float* mp = g_mem_p + ((size_t)chunk * BH_ + bh) * D_ * D_;
#pragma unroll
    for (int i = 0; i < 8; i++) {
        float o[8];
#pragma unroll
        for (int j = 0; j < 4; j++) {
            float2 v = f2unpack(acc[i][j]);
            o[2 * j] = v.x; o[2 * j + 1] = v.y;
        }
        *(float4*)(mp + (size_t)(k0 + i) * D_ + v0)     = *(float4*)&o[0];
        *(float4*)(mp + (size_t)(k0 + i) * D_ + v0 + 4) = *(float4*)&o[4];
    }
    if (tid < 128) g_nrm_p[(chunk * BH_ + bh) * D_ + tid] = nacc;
}

// ---------------------------------------------------------------------------
// Kernel 1b: reduce SPLIT_ partials, emit TRANSPOSED fp16 memory [v][k]
// ---------------------------------------------------------------------------
#define MR_SMEM_ (128 * 129 * 4)
__global__ __launch_bounds__(256) void k_mreduce() {
    extern __shared__ float sT[];                 // [128][129]
    const int bh  = blockIdx.x;
    const int tid = threadIdx.x;

    for (int i = 0; i < 16; i++) {
        int e4 = tid + i * 256;                   // float4 index (4096 total)
        float4 s = make_float4(0.f, 0.f, 0.f, 0.f);
#pragma unroll
        for (int c = 0; c < SPLIT_; c++) {
            const float4* p = (const float4*)(g_mem_p + ((size_t)(c * BH_ + bh) << 14));
            float4 t = p[e4];
            s.x += t.x; s.y += t.y; s.z += t.z; s.w += t.w;
        }
        int k = e4 >> 5;
        int v = (e4 & 31) * 4;
        sT[k * 129 + v + 0] = s.x;
        sT[k * 129 + v + 1] = s.y;
        sT[k * 129 + v + 2] = s.z;
        sT[k * 129 + v + 3] = s.w;
    }
    __syncthreads();

    uint32_t* th = (uint32_t*)(g_mem_th + (size_t)bh * D_ * D_);
    for (int i = 0; i < 32; i++) {
        int e2 = tid + i * 256;                   // half2 index (8192 total)
        int v = e2 >> 6, k = (e2 & 63) * 2;
        th[e2] = h2pack(sT[(k + 0) * 129 + v], sT[(k + 1) * 129 + v]);
    }
}

// ---------------------------------------------------------------------------
// Kernel 2: retrieved = phiQ @ memory via HMMA (B = mem^T fp16),
//           denom from the SAME fp16 phiQ, gated combine, fp16 out [b,s,h*D+d]
// Fully async front end: Qraw / mem^T / L all cp.async'd into smem.
// block = (s-tile 128, bh); 8 warps, warp tile 64(s) x 32(v)
// ---------------------------------------------------------------------------
#define RSTR_ 272                                 // 128 fp16 + 16B pad
#define R_QRAW_ 0                                 // 128x128 fp32 = 65536
#define R_QH_   65536                             // 128 x RSTR_ = 34816
#define R_MH_   (R_QH_ + 128 * RSTR_)             // 100352
#define R_L_    (R_MH_ + 128 * RSTR_)             // 135168 (+65536)
#define R_N_    (R_L_ + 65536)                    // 200704
#define R_D_    (R_N_ + 512)                      // 201216
#define RSMEM_  (R_D_ + 512)                      // 201728

__global__ __launch_bounds__(256, 1) void k_retr_mma(const float* __restrict__ Qin,
                                                     const float* __restrict__ Lin,
                                                     const float* __restrict__ bal)
{
    extern __shared__ char smem[];
    const uint32_t sb = s2u(smem);
    const int tid  = threadIdx.x;
    const int lane = tid & 31;
    const int wid  = tid >> 5;
    const int wm   = wid >> 2;                    // 0..1  (64 rows each)
    const int wn   = wid & 3;                     // 0..3  (32 cols each)
    const int bh   = blockIdx.y;
    const int s0   = blockIdx.x * 128;
    const int h    = bh & (H_ - 1);
    const int b    = bh >> 5;

    const char* Qp = (const char*)(Qin + (size_t)bh * S_ * D_ + (size_t)s0 * D_);
    const char* Lp = (const char*)(Lin + (size_t)bh * S_ * D_ + (size_t)s0 * D_);

    // 1) async Q raw (64KB contiguous)
#pragma unroll
    for (int i = 0; i < 16; i++) {
        int u = tid + i * 256;
        cp16(sb + R_QRAW_ + u * 16, Qp + u * 16);
    }
    CP_COMMIT();
    // 2) async mem^T (128 rows x 256B -> padded stride)
    {
        const char* mh = (const char*)(g_mem_th + (size_t)bh * D_ * D_);
#pragma unroll
        for (int i = 0; i < 8; i++) {
            int u = tid + i * 256;                // 2048 chunks
            int r = u >> 4, cc = u & 15;
            cp16(sb + R_MH_ + r * RSTR_ + cc * 16, mh + u * 16);
        }
    }
    CP_COMMIT();
    // 3) async L raw (64KB contiguous)
#pragma unroll
    for (int i = 0; i < 16; i++) {
        int u = tid + i * 256;
        cp16(sb + R_L_ + u * 16, Lp + u * 16);
    }
    CP_COMMIT();

    // 4) norm sums (sync loads, latency overlapped with cp.async)
    if (tid < 128) {
        float s = 0.f;
#pragma unroll
        for (int c = 0; c < SPLIT_; c++) s += g_nrm_p[(c * BH_ + bh) * D_ + tid];
        ((float*)(smem + R_N_))[tid] = s;
    }

    CP_WAIT(1);                                   // Qraw + mem^T arrived
    __syncthreads();

    // 5) convert Qraw -> phi -> fp16
#pragma unroll
    for (int i = 0; i < 16; i++) {
        int u = tid + i * 256;                    // float4 idx, 4096 total
        int r = u >> 5;
        int c = (u & 31) * 4;
        float4 q = *(const float4*)(smem + R_QRAW_ + u * 16);
        q.x = phi1(q.x); q.y = phi1(q.y);
        q.z = phi1(q.z); q.w = phi1(q.w);
        uint32_t* d = (uint32_t*)(smem + R_QH_ + r * RSTR_ + c * 2);
        d[0] = h2pack(q.x, q.y);
        d[1] = h2pack(q.z, q.w);
    }
    __syncthreads();

    // 6) denom[s] from the same fp16 phiQ
    {
        int row = tid >> 1, half = tid & 1;
        const __half* qr = (const __half*)(smem + R_QH_ + row * RSTR_) + half * 64;
        const float*  nn = (const float*)(smem + R_N_) + half * 64;
        float s = 0.f;
#pragma unroll
        for (int k = 0; k < 64; k++) s += __half2float(qr[k]) * nn[k];
        s += __shfl_xor_sync(0xFFFFFFFFu, s, 1);
        if (!half) ((float*)(smem + R_D_))[row] = s;
    }
    __syncthreads();

    // 7) HMMA: 64x32 per warp, K=128, single pass
    float acc[4][4][4];
#pragma unroll
    for (int i = 0; i < 4; i++)
#pragma unroll
        for (int j = 0; j < 4; j++)
#pragma unroll
            for (int q = 0; q < 4; q++) acc[i][j][q] = 0.f;

    const uint32_t aOff = sb + R_QH_ +
        (uint32_t)(wm * 64 + (lane & 15)) * RSTR_ + ((lane >> 4) << 4);
    const uint32_t bOff = sb + R_MH_ +
        (uint32_t)(wn * 32 + (lane & 7) + ((lane >> 4) << 3)) * RSTR_ +
        ((lane & 8) << 1);

#pragma unroll
    for (int ks = 0; ks < 8; ks++) {
        uint32_t af[4][4], bf[2][4];
#pragma unroll
        for (int mt = 0; mt < 4; mt++)
            ldx4(af[mt], aOff + (uint32_t)mt * (16 * RSTR_) + ks * 32);
#pragma unroll
        for (int p = 0; p < 2; p++)
            ldx4(bf[p], bOff + (uint32_t)p * (16 * RSTR_) + ks * 32);
#pragma unroll
        for (int mt = 0; mt < 4; mt++)
#pragma unroll
            for (int p = 0; p < 2; p++) {
                mma16816(acc[mt][2 * p],     af[mt], bf[p][0], bf[p][1]);
                mma16816(acc[mt][2 * p + 1], af[mt], bf[p][2], bf[p][3]);
            }
    }

    CP_WAIT(0);                                   // L arrived (long ago)
    __syncthreads();

    // 8) epilogue: gate + combine with local (from smem), store fp16
    float bfv = bal[h];
    float gw = 1.f / (1.f + __expf(-bfv));
    float lw = 1.f / (1.f + __expf(-(1.f - bfv)));

    __half* op = g_attn + (size_t)(b * S_ + s0) * DM_ + (size_t)h * D_;
    const float* sDen = (const float*)(smem + R_D_);
    const float* sL   = (const float*)(smem + R_L_);

#pragma unroll
    for (int mt = 0; mt < 4; mt++) {
        int r0 = wm * 64 + mt * 16 + (lane >> 2);
        float rd0 = gw / sDen[r0];
        float rd1 = gw / sDen[r0 + 8];
#pragma unroll
        for (int nt = 0; nt < 4; nt++) {
            int col = wn * 32 + nt * 8 + (lane & 3) * 2;
            float2 l0 = *(const float2*)(sL + r0 * D_ + col);
            float2 l1 = *(const float2*)(sL + (r0 + 8) * D_ + col);
            *(uint32_t*)(op + (size_t)r0 * DM_ + col) =
                h2pack(acc[mt][nt][0] * rd0 + lw * l0.x,
                       acc[mt][nt][1] * rd0 + lw * l0.y);
            *(uint32_t*)(op + (size_t)(r0 + 8) * DM_ + col) =
                h2pack(acc[mt][nt][2] * rd1 + lw * l1.x,
                       acc[mt][nt][3] * rd1 + lw * l1.y);
        }
    }
}

// ---------------------------------------------------------------------------
// Kernel 3: Out[m,n] = sum_k attn[m,k] * w_o[n,k]
// fp16 mma.sync m16n8k16, single pass. Block tile 256x128, BK=64,
// 3-stage cp.async pipeline, 512 threads = 16 warps (4m x 4n) of 64x32.
// ---------------------------------------------------------------------------
#define BM_ 256
#define BN_ 128
#define BK_ 64
#define PSTR_ 144                            // 64 fp16 = 128B + 16B pad
#define A_TILE_B_ (BM_ * PSTR_)              // 36864
#define B_TILE_B_ (BN_ * PSTR_)              // 18432
#define PBUF_ (A_TILE_B_ + B_TILE_B_)        // 55296
#define NSTG_ 3
#define PSMEM_ (NSTG_ * PBUF_)               // 165888
#define NIT_ (DM_ / BK_)                     // 64
#define PTHR_ 512

__global__ __launch_bounds__(PTHR_, 1) void k_proj_mma(float* __restrict__ Out)
{
    extern __shared__ char smem[];
    const uint32_t sbase = s2u(smem);
    const int tid  = threadIdx.x;
    const int lane = tid & 31;
    const int wid  = tid >> 5;
    const int wm   = wid >> 2;               // 0..3  (64 rows each)
    const int wn   = wid & 3;                // 0..3  (32 cols each)
    const int m0   = blockIdx.y * BM_;
    const int n0   = blockIdx.x * BN_;

    const __half* Ap = g_attn + (size_t)m0 * DM_;
    const __half* Bw = g_wo   + (size_t)n0 * DM_;

    float acc[4][4][4];
#pragma unroll
    for (int i = 0; i < 4; i++)
#pragma unroll
        for (int j = 0; j < 4; j++)
#pragma unroll
            for (int q = 0; q < 4; q++) acc[i][j][q] = 0.f;

    const uint32_t aFragOff =
        (uint32_t)(wm * 64 + (lane & 15)) * PSTR_ + ((lane >> 4) << 4);
    const uint32_t bFragOff =
        (uint32_t)(wn * 32 + (lane & 7) + ((lane >> 4) << 3)) * PSTR_ +
        ((lane & 8) << 1);

    auto load_tiles = [&](int bsel, int k0) {
        const uint32_t sbuf = sbase + (uint32_t)bsel * PBUF_;
#pragma unroll
        for (int i = 0; i < 4; i++) {        // A: 2048 chunks / 512 thr
            int u = tid + i * PTHR_;
            int r = u >> 3, ch = u & 7;
            cp16(sbuf + (uint32_t)r * PSTR_ + ch * 16,
                 Ap + (size_t)r * DM_ + k0 + ch * 8);
        }
#pragma unroll
        for (int i = 0; i < 2; i++) {        // B: 1024 chunks
            int u = tid + i * PTHR_;
            int r = u >> 3, ch = u & 7;
            cp16(sbuf + A_TILE_B_ + (uint32_t)r * PSTR_ + ch * 16,
                 Bw + (size_t)r * DM_ + k0 + ch * 8);
        }
    };

    load_tiles(0, 0);       CP_COMMIT();
    load_tiles(1, BK_);     CP_COMMIT();
    load_tiles(2, 2 * BK_); CP_COMMIT();

    int cur = 0;
    for (int it = 0; it < NIT_; it++) {
        CP_WAIT(2);
        __syncthreads();
        const uint32_t sbuf = sbase + (uint32_t)cur * PBUF_;

#pragma unroll
        for (int ks = 0; ks < 4; ks++) {
            uint32_t ah[4][4], bw[2][4];
#pragma unroll
            for (int mt = 0; mt < 4; mt++)
                ldx4(ah[mt], sbuf + aFragOff + (uint32_t)mt * (16 * PSTR_) + ks * 32);
#pragma unroll
            for (int p = 0; p < 2; p++)
                ldx4(bw[p], sbuf + A_TILE_B_ + bFragOff +
                             (uint32_t)p * (16 * PSTR_) + ks * 32);
#pragma unroll
            for (int mt = 0; mt < 4; mt++)
#pragma unroll
                for (int p = 0; p < 2; p++) {
                    mma16816(acc[mt][2 * p],     ah[mt], bw[p][0], bw[p][1]);
                    mma16816(acc[mt][2 * p + 1], ah[mt], bw[p][2], bw[p][3]);
                }
        }
        __syncthreads();
        if (it + 3 < NIT_) load_tiles(cur, (it + 3) * BK_);
        CP_COMMIT();
        cur = (cur == 2) ? 0 : cur + 1;
    }

    // ---- epilogue ----
#pragma unroll
    for (int mt = 0; mt < 4; mt++) {
        int r0 = m0 + wm * 64 + mt * 16 + (lane >> 2);
#pragma unroll
        for (int nt = 0; nt < 4; nt++) {
            int col = n0 + wn * 32 + nt * 8 + (lane & 3) * 2;
            float* p0 = Out + (size_t)r0 * DM_ + col;
            *(float2*)p0              = make_float2(acc[mt][nt][0], acc[mt][nt][1]);
            *(float2*)(p0 + 8 * DM_)  = make_float2(acc[mt][nt][2], acc[mt][nt][3]);
        }
    }
}

// ---------------------------------------------------------------------------
// kernel_launch
// inputs: 0=query, 1=key, 2=value, 3=local_attn_outputs, 4=balance, 5=w_o
// ---------------------------------------------------------------------------
extern "C" void kernel_launch(void* const* d_in, const int* in_sizes, int n_in,
                              void* d_out, int out_size)
{
    const float* Q   = (const float*)d_in[0];
    const float* K   = (const float*)d_in[1];
    const float* V   = (const float*)d_in[2];
    const float* L   = (const float*)d_in[3];
    const float* bal = (const float*)d_in[4];
    const float* Wo  = (const float*)d_in[5];
    float* out = (float*)d_out;

    cudaFuncSetAttribute(k_mreduce,  cudaFuncAttributeMaxDynamicSharedMemorySize, MR_SMEM_);
    cudaFuncSetAttribute(k_retr_mma, cudaFuncAttributeMaxDynamicSharedMemorySize, RSMEM_);
    cudaFuncSetAttribute(k_proj_mma, cudaFuncAttributeMaxDynamicSharedMemorySize, PSMEM_);

    k_cvt<<<(DM_ * DM_) / 4 / 256, 256>>>(Wo);

    dim3 g1(BH_, SPLIT_);
    k_memory<<<g1, 256>>>(K, V);
    k_mreduce<<<BH_, 256, MR_SMEM_>>>();

    dim3 g2(S_ / 128, BH_);
    k_retr_mma<<<g2, 256, RSMEM_>>>(Q, L, bal);

    dim3 g3(DM_ / BN_, M_ / BM_);     // 32 x 32
    k_proj_mma<<<g3, PTHR_, PSMEM_>>>(out);
}

// round 17
// speedup vs baseline: 5.2404x; 1.0272x over previous
#include <cuda_runtime.h>
#include <cuda_fp16.h>
#include <cstdint>

// Problem constants
#define B_  4
#define H_  32
#define S_  2048
#define D_  128
#define BH_ (B_ * H_)          // 128
#define DM_ (H_ * D_)          // 4096
#define M_  (B_ * S_)          // 8192

#define SPLIT_ 8
#define SC_ (S_ / SPLIT_)      // 256

// Scratch (device globals: no allocation allowed in kernel_launch)
__device__ float g_mem_p[SPLIT_ * BH_ * D_ * D_];            // partials       64 MB
__device__ float g_nrm_p[SPLIT_ * BH_ * D_];                 // partial norms
__device__ __half g_mem_th[(size_t)BH_ * D_ * D_];           // mem^T fp16      4 MB
__device__ __half g_attn[(size_t)M_ * DM_];                  // attn fp16      64 MB
__device__ __half g_wo[(size_t)DM_ * DM_];                   // w_o fp16       32 MB

// ---------------------------------------------------------------------------
// helpers
// ---------------------------------------------------------------------------
__device__ __forceinline__ float phi1(float x) {
    return x > 0.f ? x + 1.f : __expf(x);
}
__device__ __forceinline__ unsigned long long fdup(float x) {
    unsigned long long r;
    asm("mov.b64 %0, {%1, %2};" : "=l"(r) : "f"(x), "f"(x));
    return r;
}
__device__ __forceinline__ void ffma2(unsigned long long& acc,
                                      unsigned long long a,
                                      unsigned long long b) {
    asm("fma.rn.f32x2 %0, %1, %2, %0;" : "+l"(acc) : "l"(a), "l"(b));
}
__device__ __forceinline__ float2 f2unpack(unsigned long long v) {
    float2 r;
    asm("mov.b64 {%0, %1}, %2;" : "=f"(r.x), "=f"(r.y) : "l"(v));
    return r;
}
__device__ __forceinline__ uint32_t h2pack(float a, float b) {
    __half2 t = __floats2half2_rn(a, b);
    return *reinterpret_cast<uint32_t*>(&t);
}
__device__ __forceinline__ uint32_t s2u(const void* p) {
    uint32_t r;
    asm("{ .reg .u64 t; cvta.to.shared.u64 t, %1; cvt.u32.u64 %0, t; }" : "=r"(r) : "l"(p));
    return r;
}
__device__ __forceinline__ void cp16(uint32_t s, const void* g) {
    asm volatile("cp.async.cg.shared.global [%0], [%1], 16;" :: "r"(s), "l"(g) : "memory");
}
#define CP_COMMIT() asm volatile("cp.async.commit_group;" ::: "memory")
#define CP_WAIT(n)  asm volatile("cp.async.wait_group %0;" :: "n"(n) : "memory")

__device__ __forceinline__ void ldx4(uint32_t* r, uint32_t a) {
    asm volatile("ldmatrix.sync.aligned.m8n8.x4.shared.b16 {%0,%1,%2,%3}, [%4];"
                 : "=r"(r[0]), "=r"(r[1]), "=r"(r[2]), "=r"(r[3]) : "r"(a));
}
__device__ __forceinline__ void mma16816(float* c, const uint32_t* a,
                                         uint32_t b0, uint32_t b1) {
    asm volatile(
        "mma.sync.aligned.m16n8k16.row.col.f32.f16.f16.f32 "
        "{%0,%1,%2,%3}, {%4,%5,%6,%7}, {%8,%9}, {%0,%1,%2,%3};"
        : "+f"(c[0]), "+f"(c[1]), "+f"(c[2]), "+f"(c[3])
        : "r"(a[0]), "r"(a[1]), "r"(a[2]), "r"(a[3]), "r"(b0), "r"(b1));
}

// ---------------------------------------------------------------------------
// Kernel 1 (fused): blocks [0,1024): partial memory[chunk][bh] = phiK^T @ V
//                   blocks [1024,1280): w_o -> fp16 conversion (fills slack)
// ---------------------------------------------------------------------------
#define MEMCVT_BLOCKS_ (BH_ * SPLIT_ + 256)

__global__ __launch_bounds__(256) void k_memcvt(const float* __restrict__ Kin,
                                                const float* __restrict__ Vin,
                                                const float* __restrict__ Wo)
{
    __shared__ float sK[16][128];
    __shared__ float sV[16][128];

    const int bid = blockIdx.x;
    const int tid = threadIdx.x;

    if (bid >= BH_ * SPLIT_) {
        // ---- w_o conversion slice: 256 blocks x 64 float4/thread ----
        const int cb = bid - BH_ * SPLIT_;
        size_t base = (size_t)cb * 16384 + tid;
        const float4* src = (const float4*)Wo;
        uint2* dst = (uint2*)g_wo;
#pragma unroll 4
        for (int j = 0; j < 64; j++) {
            size_t i = base + (size_t)j * 256;
            float4 w = src[i];
            uint2 hp;
            hp.x = h2pack(w.x, w.y);
            hp.y = h2pack(w.z, w.w);
            dst[i] = hp;
        }
        return;
    }

    const int bh    = bid & (BH_ - 1);
    const int chunk = bid >> 7;
    const float* Kp = Kin + (size_t)bh * S_ * D_ + (size_t)chunk * SC_ * D_;
    const float* Vp = Vin + (size_t)bh * S_ * D_ + (size_t)chunk * SC_ * D_;
    const int tx  = tid & 15, ty = tid >> 4;
    const int k0  = ty * 8,  v0 = tx * 8;

    unsigned long long acc[8][4];
#pragma unroll
    for (int i = 0; i < 8; i++)
#pragma unroll
        for (int j = 0; j < 4; j++) acc[i][j] = 0ULL;
    float nacc = 0.f;

    for (int s0 = 0; s0 < SC_; s0 += 16) {
#pragma unroll
        for (int i = 0; i < 2; i++) {
            int slot = tid + i * 256;
            int r = slot >> 5;
            int c = (slot & 31) << 2;
            float4 kv = *(const float4*)(Kp + (size_t)(s0 + r) * D_ + c);
            kv.x = phi1(kv.x); kv.y = phi1(kv.y);
            kv.z = phi1(kv.z); kv.w = phi1(kv.w);
            *(float4*)&sK[r][c] = kv;
            *(float4*)&sV[r][c] = *(const float4*)(Vp + (size_t)(s0 + r) * D_ + c);
        }
        __syncthreads();

        if (tid < 128) {
#pragma unroll
            for (int r = 0; r < 16; r++) nacc += sK[r][tid];
        }

#pragma unroll
        for (int r = 0; r < 16; r++) {
            float a[8];
            *(float4*)&a[0] = *(float4*)&sK[r][k0];
            *(float4*)&a[4] = *(float4*)&sK[r][k0 + 4];
            ulonglong2 b01 = *(const ulonglong2*)&sV[r][v0];
            ulonglong2 b23 = *(const ulonglong2*)&sV[r][v0 + 4];
            unsigned long long Bp[4] = { b01.x, b01.y, b23.x, b23.y };
#pragma unroll
            for (int i = 0; i < 8; i++) {
                unsigned long long ad = fdup(a[i]);
#pragma unroll
                for (int j = 0; j < 4; j++) ffma2(acc[i][j], ad, Bp[j]);
            }
        }
        __syncthreads();
    }

    float* mp = g_mem_p + ((size_t)chunk * BH_ + bh) * D_ * D_;
#pragma unroll
    for (int i = 0; i < 8; i++) {
        float o[8];
#pragma unroll
        for (int j = 0; j < 4; j++) {
            float2 v = f2unpack(acc[i][j]);
            o[2 * j] = v.x; o[2 * j + 1] = v.y;
        }
        *(float4*)(mp + (size_t)(k0 + i) * D_ + v0)     = *(float4*)&o[0];
        *(float4*)(mp + (size_t)(k0 + i) * D_ + v0 + 4) = *(float4*)&o[4];
    }
    if (tid < 128) g_nrm_p[(chunk * BH_ + bh) * D_ + tid] = nacc;
}

// ---------------------------------------------------------------------------
// Kernel 1b: reduce SPLIT_ partials, emit TRANSPOSED fp16 memory [v][k]
// ---------------------------------------------------------------------------
#define MR_SMEM_ (128 * 129 * 4)
__global__ __launch_bounds__(256) void k_mreduce() {
    extern __shared__ float sT[];                 // [128][129]
    const int bh  = blockIdx.x;
    const int tid = threadIdx.x;

    for (int i = 0; i < 16; i++) {
        int e4 = tid + i * 256;                   // float4 index (4096 total)
        float4 s = make_float4(0.f, 0.f, 0.f, 0.f);
#pragma unroll
        for (int c = 0; c < SPLIT_; c++) {
            const float4* p = (const float4*)(g_mem_p + ((size_t)(c * BH_ + bh) << 14));
            float4 t = p[e4];
            s.x += t.x; s.y += t.y; s.z += t.z; s.w += t.w;
        }
        int k = e4 >> 5;
        int v = (e4 & 31) * 4;
        sT[k * 129 + v + 0] = s.x;
        sT[k * 129 + v + 1] = s.y;
        sT[k * 129 + v + 2] = s.z;
        sT[k * 129 + v + 3] = s.w;
    }
    __syncthreads();

    uint32_t* th = (uint32_t*)(g_mem_th + (size_t)bh * D_ * D_);
    for (int i = 0; i < 32; i++) {
        int e2 = tid + i * 256;                   // half2 index (8192 total)
        int v = e2 >> 6, k = (e2 & 63) * 2;
        th[e2] = h2pack(sT[(k + 0) * 129 + v], sT[(k + 1) * 129 + v]);
    }
}

// ---------------------------------------------------------------------------
// Kernel 2: retrieved = phiQ @ memory via HMMA (B = mem^T fp16),
//           denom from the SAME fp16 phiQ, gated combine, fp16 out [b,s,h*D+d]
// Slim smem (69KB -> 2 CTAs/SM): Q via LDG->phi->STS, mem via cp.async,
// L via direct LDG in epilogue.  8 warps, warp tile 64(s) x 32(v).
// ---------------------------------------------------------------------------
#define RSTR_ 272                                 // 128 fp16 + 16B pad
#define R_QH_ 0                                   // 128 x RSTR_ = 34816
#define R_MH_ (128 * RSTR_)                       // 34816
#define R_N_  (2 * 128 * RSTR_)                   // 69632
#define R_D_  (R_N_ + 512)                        // 70144
#define RSMEM_ (R_D_ + 512)                       // 70656

__global__ __launch_bounds__(256) void k_retr_mma(const float* __restrict__ Qin,
                                                  const float* __restrict__ Lin,
                                                  const float* __restrict__ bal)
{
    extern __shared__ char smem[];
    const uint32_t sb = s2u(smem);
    const int tid  = threadIdx.x;
    const int lane = tid & 31;
    const int wid  = tid >> 5;
    const int wm   = wid >> 2;                    // 0..1  (64 rows each)
    const int wn   = wid & 3;                     // 0..3  (32 cols each)
    const int bh   = blockIdx.y;
    const int s0   = blockIdx.x * 128;
    const int h    = bh & (H_ - 1);
    const int b    = bh >> 5;

    // 1) async mem^T (2048 16B chunks into padded rows)
    {
        const char* mh = (const char*)(g_mem_th + (size_t)bh * D_ * D_);
#pragma unroll
        for (int i = 0; i < 8; i++) {
            int u = tid + i * 256;
            int r = u >> 4, cc = u & 15;
            cp16(sb + R_MH_ + r * RSTR_ + cc * 16, mh + u * 16);
        }
    }
    CP_COMMIT();

    // 2) Q: LDG fp32 -> phi -> fp16 STS (16 independent loads, MLP 16)
    const float* Qp = Qin + (size_t)bh * S_ * D_ + (size_t)s0 * D_;
    {
        float4 qv[16];
#pragma unroll
        for (int i = 0; i < 16; i++) {
            int u = tid + i * 256;
            qv[i] = *(const float4*)(Qp + (size_t)(u >> 5) * D_ + (u & 31) * 4);
        }
#pragma unroll
        for (int i = 0; i < 16; i++) {
            int u = tid + i * 256;
            int r = u >> 5, c = (u & 31) * 4;
            float4 q = qv[i];
            q.x = phi1(q.x); q.y = phi1(q.y);
            q.z = phi1(q.z); q.w = phi1(q.w);
            uint32_t* d = (uint32_t*)(smem + R_QH_ + r * RSTR_ + c * 2);
            d[0] = h2pack(q.x, q.y);
            d[1] = h2pack(q.z, q.w);
        }
    }

    // 3) norm sums
    if (tid < 128) {
        float s = 0.f;
#pragma unroll
        for (int c = 0; c < SPLIT_; c++) s += g_nrm_p[(c * BH_ + bh) * D_ + tid];
        ((float*)(smem + R_N_))[tid] = s;
    }

    CP_WAIT(0);
    __syncthreads();

    // 4) denom[s] from the same fp16 phiQ
    {
        int row = tid >> 1, half = tid & 1;
        const __half* qr = (const __half*)(smem + R_QH_ + row * RSTR_) + half * 64;
        const float*  nn = (const float*)(smem + R_N_) + half * 64;
        float s = 0.f;
#pragma unroll
        for (int k = 0; k < 64; k++) s += __half2float(qr[k]) * nn[k];
        s += __shfl_xor_sync(0xFFFFFFFFu, s, 1);
        if (!half) ((float*)(smem + R_D_))[row] = s;
    }
    __syncthreads();

    // 5) HMMA: 64x32 per warp, K=128, single pass
    float acc[4][4][4];
#pragma unroll
    for (int i = 0; i < 4; i++)
#pragma unroll
        for (int j = 0; j < 4; j++)
#pragma unroll
            for (int q = 0; q < 4; q++) acc[i][j][q] = 0.f;

    const uint32_t aOff = sb + R_QH_ +
        (uint32_t)(wm * 64 + (lane & 15)) * RSTR_ + ((lane >> 4) << 4);
    const uint32_t bOff = sb + R_MH_ +
        (uint32_t)(wn * 32 + (lane & 7) + ((lane >> 4) << 3)) * RSTR_ +
        ((lane & 8) << 1);

#pragma unroll
    for (int ks = 0; ks < 8; ks++) {
        uint32_t af[4][4], bf[2][4];
#pragma unroll
        for (int mt = 0; mt < 4; mt++)
            ldx4(af[mt], aOff + (uint32_t)mt * (16 * RSTR_) + ks * 32);
#pragma unroll
        for (int p = 0; p < 2; p++)
            ldx4(bf[p], bOff + (uint32_t)p * (16 * RSTR_) + ks * 32);
#pragma unroll
        for (int mt = 0; mt < 4; mt++)
#pragma unroll
            for (int p = 0; p < 2; p++) {
                mma16816(acc[mt][2 * p],     af[mt], bf[p][0], bf[p][1]);
                mma16816(acc[mt][2 * p + 1], af[mt], bf[p][2], bf[p][3]);
            }
    }

    // 6) epilogue: gate + combine with local (direct LDG), store fp16
    float bfv = bal[h];
    float gw = 1.f / (1.f + __expf(-bfv));
    float lw = 1.f / (1.f + __expf(-(1.f - bfv)));

    const float* lp = Lin + (size_t)bh * S_ * D_ + (size_t)s0 * D_;
    __half* op = g_attn + (size_t)(b * S_ + s0) * DM_ + (size_t)h * D_;
    const float* sDen = (const float*)(smem + R_D_);

#pragma unroll
    for (int mt = 0; mt < 4; mt++) {
        int r0 = wm * 64 + mt * 16 + (lane >> 2);
        float rd0 = gw / sDen[r0];
        float rd1 = gw / sDen[r0 + 8];
#pragma unroll
        for (int nt = 0; nt < 4; nt++) {
            int col = wn * 32 + nt * 8 + (lane & 3) * 2;
            float2 l0 = *(const float2*)(lp + (size_t)r0 * D_ + col);
            float2 l1 = *(const float2*)(lp + (size_t)(r0 + 8) * D_ + col);
            *(uint32_t*)(op + (size_t)r0 * DM_ + col) =
                h2pack(acc[mt][nt][0] * rd0 + lw * l0.x,
                       acc[mt][nt][1] * rd0 + lw * l0.y);
            *(uint32_t*)(op + (size_t)(r0 + 8) * DM_ + col) =
                h2pack(acc[mt][nt][2] * rd1 + lw * l1.x,
                       acc[mt][nt][3] * rd1 + lw * l1.y);
        }
    }
}

// ---------------------------------------------------------------------------
// Kernel 3: Out[m,n] = sum_k attn[m,k] * w_o[n,k]
// fp16 mma.sync m16n8k16, single pass. Block tile 256x128, BK=64,
// 4-stage cp.async pipeline with ONE __syncthreads per iteration.
// 512 threads = 16 warps (4m x 4n) of 64x32.
// ---------------------------------------------------------------------------
#define BM_ 256
#define BN_ 128
#define BK_ 64
#define PSTR_ 144                            // 64 fp16 = 128B + 16B pad
#define A_TILE_B_ (BM_ * PSTR_)              // 36864
#define B_TILE_B_ (BN_ * PSTR_)              // 18432
#define PBUF_ (A_TILE_B_ + B_TILE_B_)        // 55296
#define NSTG_ 4
#define PSMEM_ (NSTG_ * PBUF_)               // 221184
#define NIT_ (DM_ / BK_)                     // 64
#define PTHR_ 512

__global__ __launch_bounds__(PTHR_, 1) void k_proj_mma(float* __restrict__ Out)
{
    extern __shared__ char smem[];
    const uint32_t sbase = s2u(smem);
    const int tid  = threadIdx.x;
    const int lane = tid & 31;
    const int wid  = tid >> 5;
    const int wm   = wid >> 2;               // 0..3  (64 rows each)
    const int wn   = wid & 3;                // 0..3  (32 cols each)
    const int m0   = blockIdx.y * BM_;
    const int n0   = blockIdx.x * BN_;

    const __half* Ap = g_attn + (size_t)m0 * DM_;
    const __half* Bw = g_wo   + (size_t)n0 * DM_;

    float acc[4][4][4];
#pragma unroll
    for (int i = 0; i < 4; i++)
#pragma unroll
        for (int j = 0; j < 4; j++)
#pragma unroll
            for (int q = 0; q < 4; q++) acc[i][j][q] = 0.f;

    const uint32_t aFragOff =
        (uint32_t)(wm * 64 + (lane & 15)) * PSTR_ + ((lane >> 4) << 4);
    const uint32_t bFragOff =
        (uint32_t)(wn * 32 + (lane & 7) + ((lane >> 4) << 3)) * PSTR_ +
        ((lane & 8) << 1);

    auto load_tiles = [&](int bsel, int k0) {
        const uint32_t sbuf = sbase + (uint32_t)bsel * PBUF_;
#pragma unroll
        for (int i = 0; i < 4; i++) {        // A: 2048 chunks / 512 thr
            int u = tid + i * PTHR_;
            int r = u >> 3, ch = u & 7;
            cp16(sbuf + (uint32_t)r * PSTR_ + ch * 16,
                 Ap + (size_t)r * DM_ + k0 + ch * 8);
        }
#pragma unroll
        for (int i = 0; i < 2; i++) {        // B: 1024 chunks
            int u = tid + i * PTHR_;
            int r = u >> 3, ch = u & 7;
            cp16(sbuf + A_TILE_B_ + (uint32_t)r * PSTR_ + ch * 16,
                 Bw + (size_t)r * DM_ + k0 + ch * 8);
        }
    };

    load_tiles(0, 0);       CP_COMMIT();
    load_tiles(1, BK_);     CP_COMMIT();
    load_tiles(2, 2 * BK_); CP_COMMIT();

    for (int it = 0; it < NIT_; it++) {
        CP_WAIT(2);                           // stage it%4 arrived
        __syncthreads();                      // visible to all; all past it-1
        if (it + 3 < NIT_) load_tiles((it + 3) & 3, (it + 3) * BK_);
        CP_COMMIT();

        const uint32_t sbuf = sbase + (uint32_t)(it & 3) * PBUF_;
#pragma unroll
        for (int ks = 0; ks < 4; ks++) {
            uint32_t ah[4][4], bw[2][4];
#pragma unroll
            for (int mt = 0; mt < 4; mt++)
                ldx4(ah[mt], sbuf + aFragOff + (uint32_t)mt * (16 * PSTR_) + ks * 32);
#pragma unroll
            for (int p = 0; p < 2; p++)
                ldx4(bw[p], sbuf + A_TILE_B_ + bFragOff +
                             (uint32_t)p * (16 * PSTR_) + ks * 32);
#pragma unroll
            for (int mt = 0; mt < 4; mt++)
#pragma unroll
                for (int p = 0; p < 2; p++) {
                    mma16816(acc[mt][2 * p],     ah[mt], bw[p][0], bw[p][1]);
                    mma16816(acc[mt][2 * p + 1], ah[mt], bw[p][2], bw[p][3]);
                }
        }
    }

    // ---- epilogue ----
#pragma unroll
    for (int mt = 0; mt < 4; mt++) {
        int r0 = m0 + wm * 64 + mt * 16 + (lane >> 2);
#pragma unroll
        for (int nt = 0; nt < 4; nt++) {
            int col = n0 + wn * 32 + nt * 8 + (lane & 3) * 2;
            float* p0 = Out + (size_t)r0 * DM_ + col;
            *(float2*)p0              = make_float2(acc[mt][nt][0], acc[mt][nt][1]);
            *(float2*)(p0 + 8 * DM_)  = make_float2(acc[mt][nt][2], acc[mt][nt][3]);
        }
    }
}

// ---------------------------------------------------------------------------
// kernel_launch
// inputs: 0=query, 1=key, 2=value, 3=local_attn_outputs, 4=balance, 5=w_o
// ---------------------------------------------------------------------------
extern "C" void kernel_launch(void* const* d_in, const int* in_sizes, int n_in,
                              void* d_out, int out_size)
{
    const float* Q   = (const float*)d_in[0];
    const float* K   = (const float*)d_in[1];
    const float* V   = (const float*)d_in[2];
    const float* L   = (const float*)d_in[3];
    const float* bal = (const float*)d_in[4];
    const float* Wo  = (const float*)d_in[5];
    float* out = (float*)d_out;

    cudaFuncSetAttribute(k_mreduce,  cudaFuncAttributeMaxDynamicSharedMemorySize, MR_SMEM_);
    cudaFuncSetAttribute(k_retr_mma, cudaFuncAttributeMaxDynamicSharedMemorySize, RSMEM_);
    cudaFuncSetAttribute(k_proj_mma, cudaFuncAttributeMaxDynamicSharedMemorySize, PSMEM_);

    k_memcvt<<<MEMCVT_BLOCKS_, 256>>>(K, V, Wo);
    k_mreduce<<<BH_, 256, MR_SMEM_>>>();

    dim3 g2(S_ / 128, BH_);
    k_retr_mma<<<g2, 256, RSMEM_>>>(Q, L, bal);

    dim3 g3(DM_ / BN_, M_ / BM_);     // 32 x 32
    k_proj_mma<<<g3, PTHR_, PSMEM_>>>(out);
}